// round 8
// baseline (speedup 1.0000x reference)
#include <cuda_runtime.h>
#include <cuda_bf16.h>
#include <cuda_fp16.h>
#include <cstdint>

#define BB 256
#define TT 256
#define EMB 384
#define HH 6
#define DD 64
#define BT (BB*TT)

// ---------------------------------------------------------------------------
// Scratch (__device__ globals — allocation-free rule)
// ---------------------------------------------------------------------------
__device__ __align__(16) __half g_qhi[BB * HH * TT * DD];
__device__ __align__(16) __half g_qlo[BB * HH * TT * DD];
__device__ __align__(16) __half g_khi[BB * HH * TT * DD];   // hi only (B-side)
__device__ __align__(16) __half g_vhi[BB * HH * TT * DD];   // hi only (B-side)
__device__ __align__(16) __half g_wthi[3 * HH * DD * EMB];  // [n=z*384+h*64+d][e]
__device__ __align__(16) __half g_wphi[EMB * EMB];          // [n][k]
__device__ __align__(16) __half g_atthi[BT * EMB];
__device__ __align__(16) __half g_attlo[BT * EMB];

// ---------------------------------------------------------------------------
// mma.sync / ldmatrix / cp.async helpers
// ---------------------------------------------------------------------------
__device__ __forceinline__ uint32_t smem_u32(const void* p) {
    uint32_t a;
    asm("{ .reg .u64 t; cvta.to.shared.u64 t, %1; cvt.u32.u64 %0, t; }"
        : "=r"(a) : "l"(p));
    return a;
}
__device__ __forceinline__ void ldm4(uint32_t* r, uint32_t addr) {
    asm volatile("ldmatrix.sync.aligned.m8n8.x4.shared.b16 {%0,%1,%2,%3}, [%4];"
        : "=r"(r[0]), "=r"(r[1]), "=r"(r[2]), "=r"(r[3]) : "r"(addr));
}
__device__ __forceinline__ void ldm4t(uint32_t* r, uint32_t addr) {
    asm volatile("ldmatrix.sync.aligned.m8n8.x4.trans.shared.b16 {%0,%1,%2,%3}, [%4];"
        : "=r"(r[0]), "=r"(r[1]), "=r"(r[2]), "=r"(r[3]) : "r"(addr));
}
__device__ __forceinline__ void mma_f16(float* c, const uint32_t* a, const uint32_t* b) {
    asm volatile(
        "mma.sync.aligned.m16n8k16.row.col.f32.f16.f16.f32 "
        "{%0,%1,%2,%3}, {%4,%5,%6,%7}, {%8,%9}, {%0,%1,%2,%3};"
        : "+f"(c[0]), "+f"(c[1]), "+f"(c[2]), "+f"(c[3])
        : "r"(a[0]), "r"(a[1]), "r"(a[2]), "r"(a[3]), "r"(b[0]), "r"(b[1]));
}
// fp16-accumulate variant: {c0,c1} = 4 halves (row r cols c,c+1 ; row r+8 cols c,c+1)
__device__ __forceinline__ void mma_f16acc(uint32_t* c, const uint32_t* a, const uint32_t* b) {
    asm volatile(
        "mma.sync.aligned.m16n8k16.row.col.f16.f16.f16.f16 "
        "{%0,%1}, {%2,%3,%4,%5}, {%6,%7}, {%0,%1};"
        : "+r"(c[0]), "+r"(c[1])
        : "r"(a[0]), "r"(a[1]), "r"(a[2]), "r"(a[3]), "r"(b[0]), "r"(b[1]));
}
__device__ __forceinline__ void cp16(uint32_t dst, const void* src) {
    asm volatile("cp.async.cg.shared.global [%0], [%1], 16;" :: "r"(dst), "l"(src));
}
#define CP_COMMIT() asm volatile("cp.async.commit_group;" ::: "memory")
#define CP_WAIT_ALL() asm volatile("cp.async.wait_group 0;" ::: "memory")

__device__ __forceinline__ uint32_t pack_h2(float lo, float hi) {
    __half2 h = __floats2half2_rn(lo, hi);
    return *(uint32_t*)&h;
}
__device__ __forceinline__ uint32_t resid_h2(uint32_t u, float lo, float hi) {
    __half2 h = *(__half2*)&u;
    float2 f = __half22float2(h);
    return pack_h2(lo - f.x, hi - f.y);
}
// split 8 fp32 into fp16 hi (uint4) + fp16 lo (uint4)
__device__ __forceinline__ void split8(float4 f0, float4 f1, uint4& hi, uint4& lo) {
    __half2 h0 = __floats2half2_rn(f0.x, f0.y);
    __half2 h1 = __floats2half2_rn(f0.z, f0.w);
    __half2 h2 = __floats2half2_rn(f1.x, f1.y);
    __half2 h3 = __floats2half2_rn(f1.z, f1.w);
    float2 b0 = __half22float2(h0), b1 = __half22float2(h1);
    float2 b2 = __half22float2(h2), b3 = __half22float2(h3);
    __half2 l0 = __floats2half2_rn(f0.x - b0.x, f0.y - b0.y);
    __half2 l1 = __floats2half2_rn(f0.z - b1.x, f0.w - b1.y);
    __half2 l2 = __floats2half2_rn(f1.x - b2.x, f1.y - b2.y);
    __half2 l3 = __floats2half2_rn(f1.z - b3.x, f1.w - b3.y);
    hi = make_uint4(*(uint32_t*)&h0, *(uint32_t*)&h1, *(uint32_t*)&h2, *(uint32_t*)&h3);
    lo = make_uint4(*(uint32_t*)&l0, *(uint32_t*)&l1, *(uint32_t*)&l2, *(uint32_t*)&l3);
}

// 64B-row tile swizzle (4 units of 16B): u ^ ((r>>1)&3)
__device__ __forceinline__ uint32_t swz(uint32_t r, uint32_t u) {
    return (r << 6) + ((u ^ ((r >> 1) & 3u)) << 4);
}
// 128B-row tile swizzle (8 units of 16B): u ^ (r&7)
__device__ __forceinline__ uint32_t swz8(uint32_t r, uint32_t u) {
    return (r << 7) + ((u ^ (r & 7u)) << 4);
}

// ---------------------------------------------------------------------------
// Prep: weights only (x split is fused into the qkv GEMM now)
// ---------------------------------------------------------------------------
#define NW1 (3 * HH * DD * EMB)
__global__ void prep_weights(const float* __restrict__ wq, const float* __restrict__ wk,
                             const float* __restrict__ wv, const float* __restrict__ wp) {
    int i = blockIdx.x * 256 + threadIdx.x;
    if (i < NW1) {
        int e = i % EMB;
        int d = (i / EMB) % DD;
        int h = (i / (EMB * DD)) % HH;
        int z = i / (EMB * DD * HH);
        const float* w = (z == 0) ? wq : (z == 1) ? wk : wv;
        g_wthi[i] = __float2half(w[(h * EMB + e) * DD + d]);
    } else if (i < NW1 + EMB * EMB) {
        int j = i - NW1;
        int k = j % EMB;
        int n = j / EMB;
        g_wphi[j] = __float2half(wp[k * EMB + n]);
    }
}

// ---------------------------------------------------------------------------
// QKV GEMM: fp16 2-term, lo-term accumulated in fp16 HMMA (rate probe).
// A = x (fp32, split in-kernel), B = g_wthi.  C[M,1152] = A[M,384] x B.
// ---------------------------------------------------------------------------
#define QST 24576
#define QOFF_AH 0
#define QOFF_AL 8192
#define QOFF_BH 16384

__global__ __launch_bounds__(256) void gemm_qkv(const float* __restrict__ x)
{
    extern __shared__ char sm[];
    const uint32_t sb = smem_u32(sm);
    const char* BhiB = (const char*)g_wthi;

    const int tid  = threadIdx.x;
    const int wid  = tid >> 5;
    const int lane = tid & 31;
    const int m0   = blockIdx.y * 128;
    const int n0   = blockIdx.x * 128;

    const int lr = tid >> 2;
    const int lu = tid & 3;

    const int wm   = (wid >> 1) * 32;
    const int wn   = (wid & 1) * 64;
    const int a_r  = wm + (lane & 15);
    const int a_u0 = (lane >> 4);
    const int b_r  = wn + ((lane >> 4) & 1) * 8 + (lane & 7);
    const int b_u0 = (lane >> 3) & 1;

    float cm[2][8][4];
    uint32_t cl[2][8][2];
    #pragma unroll
    for (int mt = 0; mt < 2; mt++)
        #pragma unroll
        for (int nt = 0; nt < 8; nt++) {
            #pragma unroll
            for (int q = 0; q < 4; q++) cm[mt][nt][q] = 0.0f;
            cl[mt][nt][0] = 0u; cl[mt][nt][1] = 0u;
        }

    // prologue: chunk 0 (k elems 0..31; per thread 8 fp32)
    {
        #pragma unroll
        for (int j = 0; j < 2; j++) {
            int r = lr + j * 64;
            const float* xa = x + (size_t)(m0 + r) * EMB + lu * 8;
            float4 f0 = *(const float4*)xa;
            float4 f1 = *(const float4*)(xa + 4);
            uint4 hi, lo;
            split8(f0, f1, hi, lo);
            *(uint4*)(sm + QOFF_AH + swz(r, lu)) = hi;
            *(uint4*)(sm + QOFF_AL + swz(r, lu)) = lo;
            *(uint4*)(sm + QOFF_BH + swz(r, lu)) =
                *(const uint4*)(BhiB + (size_t)(n0 + r) * 768 + lu * 16);
        }
    }
    __syncthreads();

    int stage = 0;
    for (int kc = 0; kc < 12; kc++) {
        float4 vx[4];
        uint4 vb[2];
        if (kc < 11) {
            const int ko = (kc + 1) * 32;
            #pragma unroll
            for (int j = 0; j < 2; j++) {
                int r = lr + j * 64;
                const float* xa = x + (size_t)(m0 + r) * EMB + ko + lu * 8;
                vx[j * 2 + 0] = *(const float4*)xa;
                vx[j * 2 + 1] = *(const float4*)(xa + 4);
                vb[j] = *(const uint4*)(BhiB + (size_t)(n0 + r) * 768 + (kc + 1) * 64 + lu * 16);
            }
        }

        const uint32_t base = sb + stage * QST;
        #pragma unroll
        for (int ks = 0; ks < 2; ks++) {
            uint32_t ahi[2][4], alo[2][4], bhi[8][2];
            #pragma unroll
            for (int mt = 0; mt < 2; mt++) {
                uint32_t r = a_r + mt * 16;
                uint32_t u = ks * 2 + a_u0;
                ldm4(ahi[mt], base + QOFF_AH + swz(r, u));
                ldm4(alo[mt], base + QOFF_AL + swz(r, u));
            }
            #pragma unroll
            for (int p = 0; p < 4; p++) {
                uint32_t r = b_r + p * 16;
                uint32_t u = ks * 2 + b_u0;
                uint32_t t4[4];
                ldm4(t4, base + QOFF_BH + swz(r, u));
                bhi[2 * p][0] = t4[0]; bhi[2 * p][1] = t4[1];
                bhi[2 * p + 1][0] = t4[2]; bhi[2 * p + 1][1] = t4[3];
            }
            #pragma unroll
            for (int mt = 0; mt < 2; mt++)
                #pragma unroll
                for (int nt = 0; nt < 8; nt++) {
                    mma_f16(cm[mt][nt], ahi[mt], bhi[nt]);
                    mma_f16acc(cl[mt][nt], alo[mt], bhi[nt]);
                }
        }

        if (kc < 11) {
            char* dst = sm + (stage ^ 1) * QST;
            #pragma unroll
            for (int j = 0; j < 2; j++) {
                int r = lr + j * 64;
                uint4 hi, lo;
                split8(vx[j * 2], vx[j * 2 + 1], hi, lo);
                *(uint4*)(dst + QOFF_AH + swz(r, lu)) = hi;
                *(uint4*)(dst + QOFF_AL + swz(r, lu)) = lo;
                *(uint4*)(dst + QOFF_BH + swz(r, lu)) = vb[j];
            }
        }
        __syncthreads();
        stage ^= 1;
    }

    // epilogue: add fp16 lo-accum, write q hi/lo, k hi, v hi (q scaled 1/8)
    const int row0 = lane >> 2;
    const int col0 = (lane & 3) * 2;
    const int z = n0 / 384;
    const int nloc = n0 % 384;
    const float scl = (z == 0) ? 0.125f : 1.0f;
    __half* dhi = (z == 0) ? g_qhi : (z == 1) ? g_khi : g_vhi;
    #pragma unroll
    for (int mt = 0; mt < 2; mt++)
        #pragma unroll
        for (int half = 0; half < 2; half++) {
            int m = m0 + wm + mt * 16 + row0 + half * 8;
            int b = m >> 8, t = m & 255;
            #pragma unroll
            for (int nt = 0; nt < 8; nt++) {
                int n = nloc + wn + nt * 8 + col0;
                int h = n >> 6, d = n & 63;
                size_t idx = (((size_t)b * HH + h) * TT + t) * DD + d;
                float2 lo2 = __half22float2(*(__half2*)&cl[mt][nt][half]);
                float v0 = (cm[mt][nt][half * 2]     + lo2.x) * scl;
                float v1 = (cm[mt][nt][half * 2 + 1] + lo2.y) * scl;
                uint32_t hp = pack_h2(v0, v1);
                *(uint32_t*)(dhi + idx) = hp;
                if (z == 0)
                    *(uint32_t*)(g_qlo + idx) = resid_h2(hp, v0, v1);
            }
        }
}

// ---------------------------------------------------------------------------
// Output projection GEMM: fp16 2-term (R7-proven skeleton, f32 accum both terms)
// ---------------------------------------------------------------------------
__global__ __launch_bounds__(256, 2) void gemm_proj(const float* __restrict__ bias,
                                                    float* __restrict__ outp)
{
    extern __shared__ char sm[];
    const uint32_t sb = smem_u32(sm);

    const char* AhiB = (const char*)g_atthi;
    const char* AloB = (const char*)g_attlo;
    const char* BhiB = (const char*)g_wphi;

    const int tid  = threadIdx.x;
    const int wid  = tid >> 5;
    const int lane = tid & 31;
    const int m0   = blockIdx.y * 128;
    const int n0   = blockIdx.x * 128;

    const int lr = tid >> 2;
    const int lu = tid & 3;

    const int wm   = (wid >> 1) * 32;
    const int wn   = (wid & 1) * 64;
    const int a_r  = wm + (lane & 15);
    const int a_u0 = (lane >> 4);
    const int b_r  = wn + ((lane >> 4) & 1) * 8 + (lane & 7);
    const int b_u0 = (lane >> 3) & 1;

    float c[2][8][4];
    #pragma unroll
    for (int mt = 0; mt < 2; mt++)
        #pragma unroll
        for (int nt = 0; nt < 8; nt++)
            #pragma unroll
            for (int q = 0; q < 4; q++) c[mt][nt][q] = 0.0f;

    {
        #pragma unroll
        for (int j = 0; j < 2; j++) {
            int r = lr + j * 64;
            size_t ga = (size_t)(m0 + r) * 768 + lu * 16;
            size_t gb = (size_t)(n0 + r) * 768 + lu * 16;
            *(uint4*)(sm + QOFF_AH + swz(r, lu)) = *(const uint4*)(AhiB + ga);
            *(uint4*)(sm + QOFF_AL + swz(r, lu)) = *(const uint4*)(AloB + ga);
            *(uint4*)(sm + QOFF_BH + swz(r, lu)) = *(const uint4*)(BhiB + gb);
        }
    }
    __syncthreads();

    int stage = 0;
    for (int kc = 0; kc < 12; kc++) {
        uint4 v[6];
        if (kc < 11) {
            const int ko = (kc + 1) * 64;
            #pragma unroll
            for (int j = 0; j < 2; j++) {
                int r = lr + j * 64;
                size_t ga = (size_t)(m0 + r) * 768 + ko + lu * 16;
                size_t gb = (size_t)(n0 + r) * 768 + ko + lu * 16;
                v[j * 3 + 0] = *(const uint4*)(AhiB + ga);
                v[j * 3 + 1] = *(const uint4*)(AloB + ga);
                v[j * 3 + 2] = *(const uint4*)(BhiB + gb);
            }
        }

        const uint32_t base = sb + stage * QST;
        #pragma unroll
        for (int ks = 0; ks < 2; ks++) {
            uint32_t ahi[2][4], alo[2][4], bhi[8][2];
            #pragma unroll
            for (int mt = 0; mt < 2; mt++) {
                uint32_t r = a_r + mt * 16;
                uint32_t u = ks * 2 + a_u0;
                ldm4(ahi[mt], base + QOFF_AH + swz(r, u));
                ldm4(alo[mt], base + QOFF_AL + swz(r, u));
            }
            #pragma unroll
            for (int p = 0; p < 4; p++) {
                uint32_t r = b_r + p * 16;
                uint32_t u = ks * 2 + b_u0;
                uint32_t t4[4];
                ldm4(t4, base + QOFF_BH + swz(r, u));
                bhi[2 * p][0] = t4[0]; bhi[2 * p][1] = t4[1];
                bhi[2 * p + 1][0] = t4[2]; bhi[2 * p + 1][1] = t4[3];
            }
            #pragma unroll
            for (int mt = 0; mt < 2; mt++)
                #pragma unroll
                for (int nt = 0; nt < 8; nt++) {
                    mma_f16(c[mt][nt], ahi[mt], bhi[nt]);
                    mma_f16(c[mt][nt], alo[mt], bhi[nt]);
                }
        }

        if (kc < 11) {
            char* dst = sm + (stage ^ 1) * QST;
            #pragma unroll
            for (int j = 0; j < 2; j++) {
                int r = lr + j * 64;
                *(uint4*)(dst + QOFF_AH + swz(r, lu)) = v[j * 3 + 0];
                *(uint4*)(dst + QOFF_AL + swz(r, lu)) = v[j * 3 + 1];
                *(uint4*)(dst + QOFF_BH + swz(r, lu)) = v[j * 3 + 2];
            }
        }
        __syncthreads();
        stage ^= 1;
    }

    const int row0 = lane >> 2;
    const int col0 = (lane & 3) * 2;
    #pragma unroll
    for (int mt = 0; mt < 2; mt++)
        #pragma unroll
        for (int half = 0; half < 2; half++) {
            int m = m0 + wm + mt * 16 + row0 + half * 8;
            #pragma unroll
            for (int nt = 0; nt < 8; nt++) {
                int n = n0 + wn + nt * 8 + col0;
                float2 val = make_float2(c[mt][nt][half * 2] + bias[n],
                                         c[mt][nt][half * 2 + 1] + bias[n + 1]);
                *(float2*)(outp + (size_t)m * EMB + n) = val;
            }
        }
}

// ---------------------------------------------------------------------------
// fp16 flash attention, 2-term — exact R7-proven version.
// ---------------------------------------------------------------------------
#define AQHI 0
#define AQLO 16384
#define AKV0 32768
#define ATT_SMEM 98304

__global__ __launch_bounds__(256) void attn_tc()
{
    extern __shared__ char sm[];
    const uint32_t sb = smem_u32(sm);
    const int qt  = blockIdx.x;
    const int bh  = blockIdx.y;
    const int tid = threadIdx.x;
    const int wid = tid >> 5;
    const int lane = tid & 31;

    const __half* qhi = g_qhi + ((size_t)bh * TT + qt * 128) * DD;
    const __half* qlo = g_qlo + ((size_t)bh * TT + qt * 128) * DD;
    const __half* khi = g_khi + (size_t)bh * TT * DD;
    const __half* vhi = g_vhi + (size_t)bh * TT * DD;

    #pragma unroll
    for (int j = 0; j < 8; j++) {
        int idx = tid + 256 * j;
        int arr = idx >> 10;
        int r = (idx >> 3) & 127;
        int u = idx & 7;
        const __half* src = arr ? qlo : qhi;
        cp16(sb + (arr ? AQLO : AQHI) + swz8(r, u), src + (size_t)r * DD + u * 8);
    }
    #pragma unroll
    for (int j = 0; j < 8; j++) {
        int idx = tid + 256 * j;
        int arr = idx >> 10;
        int r = (idx >> 3) & 127;
        int u = idx & 7;
        const __half* src = arr ? vhi : khi;
        cp16(sb + AKV0 + arr * 16384 + swz8(r, u), src + (size_t)r * DD + u * 8);
    }
    CP_COMMIT();
    CP_WAIT_ALL();
    __syncthreads();

    uint32_t qfh[4][4], qfl[4][4];
    {
        int ar = wid * 16 + (lane & 15);
        #pragma unroll
        for (int kc = 0; kc < 4; kc++) {
            int u = kc * 2 + (lane >> 4);
            ldm4(qfh[kc], sb + AQHI + swz8(ar, u));
            ldm4(qfl[kc], sb + AQLO + swz8(ar, u));
        }
    }

    float o[8][4];
    #pragma unroll
    for (int nt = 0; nt < 8; nt++)
        #pragma unroll
        for (int q = 0; q < 4; q++) o[nt][q] = 0.0f;
    float mx[2] = {-1e30f, -1e30f};
    float lsum[2] = {0.0f, 0.0f};

    for (int kt = 0; kt <= qt; kt++) {
        const uint32_t kvb = sb + AKV0 + (kt & 1) * 32768;

        if (kt < qt) {
            #pragma unroll
            for (int j = 0; j < 8; j++) {
                int idx = tid + 256 * j;
                int arr = idx >> 10;
                int r = (idx >> 3) & 127;
                int u = idx & 7;
                const __half* src = arr ? vhi : khi;
                cp16(sb + AKV0 + ((kt + 1) & 1) * 32768 + arr * 16384 + swz8(r, u),
                     src + ((size_t)(kt + 1) * 128 + r) * DD + u * 8);
            }
            CP_COMMIT();
        }

        float s[16][4];
        #pragma unroll
        for (int nt = 0; nt < 16; nt++)
            #pragma unroll
            for (int q = 0; q < 4; q++) s[nt][q] = 0.0f;

        #pragma unroll
        for (int np = 0; np < 8; np++) {
            int br = np * 16 + ((lane >> 4) & 1) * 8 + (lane & 7);
            #pragma unroll
            for (int kc = 0; kc < 4; kc++) {
                int u = kc * 2 + ((lane >> 3) & 1);
                uint32_t th[4];
                ldm4(th, kvb + swz8(br, u));
                uint32_t b0h[2] = {th[0], th[1]}, b1h[2] = {th[2], th[3]};
                mma_f16(s[2 * np], qfh[kc], b0h);
                mma_f16(s[2 * np], qfl[kc], b0h);
                mma_f16(s[2 * np + 1], qfh[kc], b1h);
                mma_f16(s[2 * np + 1], qfl[kc], b1h);
            }
        }

        if (kt == qt) {
            #pragma unroll
            for (int nt = 0; nt < 16; nt++)
                #pragma unroll
                for (int q = 0; q < 4; q++) {
                    int col = nt * 8 + (lane & 3) * 2 + (q & 1);
                    int row = wid * 16 + (lane >> 2) + (q >> 1) * 8;
                    if (col > row) s[nt][q] = -1e30f;
                }
        }

        float al[2];
        #pragma unroll
        for (int hf = 0; hf < 2; hf++) {
            float rm = -1e30f;
            #pragma unroll
            for (int nt = 0; nt < 16; nt++)
                rm = fmaxf(rm, fmaxf(s[nt][hf * 2], s[nt][hf * 2 + 1]));
            rm = fmaxf(rm, __shfl_xor_sync(0xffffffffu, rm, 1));
            rm = fmaxf(rm, __shfl_xor_sync(0xffffffffu, rm, 2));
            float mn = fmaxf(mx[hf], rm);
            al[hf] = __expf(mx[hf] - mn);
            mx[hf] = mn;
            float ps = 0.0f;
            #pragma unroll
            for (int nt = 0; nt < 16; nt++) {
                s[nt][hf * 2]     = __expf(s[nt][hf * 2] - mn);
                s[nt][hf * 2 + 1] = __expf(s[nt][hf * 2 + 1] - mn);
                ps += s[nt][hf * 2] + s[nt][hf * 2 + 1];
            }
            ps += __shfl_xor_sync(0xffffffffu, ps, 1);
            ps += __shfl_xor_sync(0xffffffffu, ps, 2);
            lsum[hf] = lsum[hf] * al[hf] + ps;
        }
        #pragma unroll
        for (int nt = 0; nt < 8; nt++) {
            o[nt][0] *= al[0]; o[nt][1] *= al[0];
            o[nt][2] *= al[1]; o[nt][3] *= al[1];
        }

        #pragma unroll
        for (int kc = 0; kc < 8; kc++) {
            uint32_t ah[4], al4[4];
            ah[0] = pack_h2(s[2 * kc][0], s[2 * kc][1]);
            ah[1] = pack_h2(s[2 * kc][2], s[2 * kc][3]);
            ah[2] = pack_h2(s[2 * kc + 1][0], s[2 * kc + 1][1]);
            ah[3] = pack_h2(s[2 * kc + 1][2], s[2 * kc + 1][3]);
            al4[0] = resid_h2(ah[0], s[2 * kc][0], s[2 * kc][1]);
            al4[1] = resid_h2(ah[1], s[2 * kc][2], s[2 * kc][3]);
            al4[2] = resid_h2(ah[2], s[2 * kc + 1][0], s[2 * kc + 1][1]);
            al4[3] = resid_h2(ah[3], s[2 * kc + 1][2], s[2 * kc + 1][3]);

            int vr = kc * 16 + ((lane >> 3) & 1) * 8 + (lane & 7);
            #pragma unroll
            for (int ntp = 0; ntp < 4; ntp++) {
                int u = ntp * 2 + (lane >> 4);
                uint32_t th[4];
                ldm4t(th, kvb + 16384 + swz8(vr, u));
                uint32_t b0h[2] = {th[0], th[1]}, b1h[2] = {th[2], th[3]};
                mma_f16(o[2 * ntp], ah, b0h);
                mma_f16(o[2 * ntp], al4, b0h);
                mma_f16(o[2 * ntp + 1], ah, b1h);
                mma_f16(o[2 * ntp + 1], al4, b1h);
            }
        }

        if (kt < qt) {
            CP_WAIT_ALL();
            __syncthreads();
        }
    }

    const int b = bh / HH, h = bh % HH;
    #pragma unroll
    for (int hf = 0; hf < 2; hf++) {
        float inv = 1.0f / lsum[hf];
        int t = qt * 128 + wid * 16 + (lane >> 2) + hf * 8;
        size_t rowb = ((size_t)b * TT + t) * EMB + h * 64 + (lane & 3) * 2;
        #pragma unroll
        for (int nt = 0; nt < 8; nt++) {
            float v0 = o[nt][hf * 2] * inv;
            float v1 = o[nt][hf * 2 + 1] * inv;
            uint32_t hp = pack_h2(v0, v1);
            *(uint32_t*)(g_atthi + rowb + nt * 8) = hp;
            *(uint32_t*)(g_attlo + rowb + nt * 8) = resid_h2(hp, v0, v1);
        }
    }
}

// ---------------------------------------------------------------------------
extern "C" void kernel_launch(void* const* d_in, const int* in_sizes, int n_in,
                              void* d_out, int out_size)
{
    const float* x      = (const float*)d_in[0];
    const float* wq     = (const float*)d_in[1];
    const float* wk     = (const float*)d_in[2];
    const float* wv     = (const float*)d_in[3];
    const float* w_proj = (const float*)d_in[4];
    const float* b_proj = (const float*)d_in[5];
    float* out = (float*)d_out;

    cudaFuncSetAttribute(gemm_qkv, cudaFuncAttributeMaxDynamicSharedMemorySize, 2 * QST);
    cudaFuncSetAttribute(gemm_proj, cudaFuncAttributeMaxDynamicSharedMemorySize, 2 * QST);
    cudaFuncSetAttribute(attn_tc, cudaFuncAttributeMaxDynamicSharedMemorySize, ATT_SMEM);

    prep_weights<<<(NW1 + EMB * EMB + 255) / 256, 256>>>(wq, wk, wv, w_proj);

    gemm_qkv<<<dim3(1152 / 128, BT / 128), 256, 2 * QST>>>(x);
    attn_tc<<<dim3(TT / 128, BB * HH), 256, ATT_SMEM>>>();
    gemm_proj<<<dim3(EMB / 128, BT / 128), 256, 2 * QST>>>(b_proj, out);
}

// round 9
// speedup vs baseline: 1.2068x; 1.2068x over previous
#include <cuda_runtime.h>
#include <cuda_bf16.h>
#include <cuda_fp16.h>
#include <cstdint>

#define BB 256
#define TT 256
#define EMB 384
#define HH 6
#define DD 64
#define BT (BB*TT)

// ---------------------------------------------------------------------------
// Scratch (__device__ globals — allocation-free rule).  All fp16.
// ---------------------------------------------------------------------------
__device__ __align__(16) __half g_qhi[BB * HH * TT * DD];
__device__ __align__(16) __half g_qlo[BB * HH * TT * DD];
__device__ __align__(16) __half g_khi[BB * HH * TT * DD];   // hi only (B-side)
__device__ __align__(16) __half g_vhi[BB * HH * TT * DD];   // hi only (B-side)
__device__ __align__(16) __half g_xhi[BT * EMB];
__device__ __align__(16) __half g_xlo[BT * EMB];
__device__ __align__(16) __half g_wthi[3 * HH * DD * EMB];  // [n=z*384+h*64+d][e]
__device__ __align__(16) __half g_wphi[EMB * EMB];          // [n][k] hi only
__device__ __align__(16) __half g_atthi[BT * EMB];
__device__ __align__(16) __half g_attlo[BT * EMB];

// ---------------------------------------------------------------------------
// mma.sync / ldmatrix / cp.async helpers
// ---------------------------------------------------------------------------
__device__ __forceinline__ uint32_t smem_u32(const void* p) {
    uint32_t a;
    asm("{ .reg .u64 t; cvta.to.shared.u64 t, %1; cvt.u32.u64 %0, t; }"
        : "=r"(a) : "l"(p));
    return a;
}
__device__ __forceinline__ void ldm4(uint32_t* r, uint32_t addr) {
    asm volatile("ldmatrix.sync.aligned.m8n8.x4.shared.b16 {%0,%1,%2,%3}, [%4];"
        : "=r"(r[0]), "=r"(r[1]), "=r"(r[2]), "=r"(r[3]) : "r"(addr));
}
__device__ __forceinline__ void ldm4t(uint32_t* r, uint32_t addr) {
    asm volatile("ldmatrix.sync.aligned.m8n8.x4.trans.shared.b16 {%0,%1,%2,%3}, [%4];"
        : "=r"(r[0]), "=r"(r[1]), "=r"(r[2]), "=r"(r[3]) : "r"(addr));
}
__device__ __forceinline__ void mma_f16(float* c, const uint32_t* a, const uint32_t* b) {
    asm volatile(
        "mma.sync.aligned.m16n8k16.row.col.f32.f16.f16.f32 "
        "{%0,%1,%2,%3}, {%4,%5,%6,%7}, {%8,%9}, {%0,%1,%2,%3};"
        : "+f"(c[0]), "+f"(c[1]), "+f"(c[2]), "+f"(c[3])
        : "r"(a[0]), "r"(a[1]), "r"(a[2]), "r"(a[3]), "r"(b[0]), "r"(b[1]));
}
__device__ __forceinline__ void cp16(uint32_t dst, const void* src) {
    asm volatile("cp.async.cg.shared.global [%0], [%1], 16;" :: "r"(dst), "l"(src));
}
#define CP_COMMIT() asm volatile("cp.async.commit_group;" ::: "memory")
#define CP_WAIT_ALL() asm volatile("cp.async.wait_group 0;" ::: "memory")

// fp16x2 pack: .x = lo arg, .y = hi arg
__device__ __forceinline__ uint32_t pack_h2(float lo, float hi) {
    __half2 h = __floats2half2_rn(lo, hi);
    return *(uint32_t*)&h;
}
__device__ __forceinline__ uint32_t resid_h2(uint32_t u, float lo, float hi) {
    __half2 h = *(__half2*)&u;
    float2 f = __half22float2(h);
    return pack_h2(lo - f.x, hi - f.y);
}

// 64B-row tile swizzle (4 units of 16B): u ^ ((r>>1)&3)
__device__ __forceinline__ uint32_t swz(uint32_t r, uint32_t u) {
    return (r << 6) + ((u ^ ((r >> 1) & 3u)) << 4);
}
// 128B-row tile swizzle (8 units of 16B): u ^ (r&7)
__device__ __forceinline__ uint32_t swz8(uint32_t r, uint32_t u) {
    return (r << 7) + ((u ^ (r & 7u)) << 4);
}

// ---------------------------------------------------------------------------
// Prep kernels (R7-proven)
// ---------------------------------------------------------------------------
__global__ void prep_x(const float* __restrict__ x) {
    int i = blockIdx.x * 256 + threadIdx.x;
    if (i < BT * EMB) {
        float v = x[i];
        __half h = __float2half(v);
        g_xhi[i] = h;
        g_xlo[i] = __float2half(v - __half2float(h));
    }
}
__global__ void prep_w(const float* __restrict__ wq, const float* __restrict__ wk,
                       const float* __restrict__ wv) {
    int i = blockIdx.x * 256 + threadIdx.x;
    if (i >= 3 * HH * DD * EMB) return;
    int e = i % EMB;
    int d = (i / EMB) % DD;
    int h = (i / (EMB * DD)) % HH;
    int z = i / (EMB * DD * HH);
    const float* w = (z == 0) ? wq : (z == 1) ? wk : wv;
    g_wthi[i] = __float2half(w[(h * EMB + e) * DD + d]);
}
__global__ void prep_wp(const float* __restrict__ wp) {
    int i = blockIdx.x * 256 + threadIdx.x;
    if (i >= EMB * EMB) return;
    int k = i % EMB;
    int n = i / EMB;
    g_wphi[i] = __float2half(wp[k * EMB + n]);
}

// ---------------------------------------------------------------------------
// fp16 GEMM (R7-proven skeleton).  C[M,N] = A[M,384] x B[384,N].
// MODE 0: qkv — lo-term MMAs run ONLY for the Q tiles (n0 < 384);
//         K/V computed 1-term (they are consumed as fp16-rounded anyway).
// MODE 1: proj — 2-term everywhere; adds bias, writes fp32 out.
// ---------------------------------------------------------------------------
#define QST 24576
#define QOFF_AH 0
#define QOFF_AL 8192
#define QOFF_BH 16384

template<int MODE>
__global__ __launch_bounds__(256, 2) void gemm_f16(const float* __restrict__ bias,
                                                   float* __restrict__ outp)
{
    extern __shared__ char sm[];
    const uint32_t sb = smem_u32(sm);

    const char* AhiB = (const char*)(MODE == 0 ? g_xhi : g_atthi);
    const char* AloB = (const char*)(MODE == 0 ? g_xlo : g_attlo);
    const char* BhiB = (const char*)(MODE == 0 ? g_wthi : g_wphi);

    const int tid  = threadIdx.x;
    const int wid  = tid >> 5;
    const int lane = tid & 31;
    const int m0   = blockIdx.y * 128;
    const int n0   = blockIdx.x * 128;

    // lo-term needed?  qkv: only for Q tiles.  proj: always.
    const bool lo_on = (MODE == 1) || (n0 < 384);

    const int lr = tid >> 2;
    const int lu = tid & 3;

    const int wm   = (wid >> 1) * 32;
    const int wn   = (wid & 1) * 64;
    const int a_r  = wm + (lane & 15);
    const int a_u0 = (lane >> 4);
    const int b_r  = wn + ((lane >> 4) & 1) * 8 + (lane & 7);
    const int b_u0 = (lane >> 3) & 1;

    float c[2][8][4];
    #pragma unroll
    for (int mt = 0; mt < 2; mt++)
        #pragma unroll
        for (int nt = 0; nt < 8; nt++)
            #pragma unroll
            for (int q = 0; q < 4; q++) c[mt][nt][q] = 0.0f;

    {
        #pragma unroll
        for (int j = 0; j < 2; j++) {
            int r = lr + j * 64;
            size_t ga = (size_t)(m0 + r) * 768 + lu * 16;
            size_t gb = (size_t)(n0 + r) * 768 + lu * 16;
            *(uint4*)(sm + QOFF_AH + swz(r, lu)) = *(const uint4*)(AhiB + ga);
            *(uint4*)(sm + QOFF_AL + swz(r, lu)) = *(const uint4*)(AloB + ga);
            *(uint4*)(sm + QOFF_BH + swz(r, lu)) = *(const uint4*)(BhiB + gb);
        }
    }
    __syncthreads();

    int stage = 0;
    for (int kc = 0; kc < 12; kc++) {
        uint4 v[6];
        if (kc < 11) {
            const int ko = (kc + 1) * 64;
            #pragma unroll
            for (int j = 0; j < 2; j++) {
                int r = lr + j * 64;
                size_t ga = (size_t)(m0 + r) * 768 + ko + lu * 16;
                size_t gb = (size_t)(n0 + r) * 768 + ko + lu * 16;
                v[j * 3 + 0] = *(const uint4*)(AhiB + ga);
                v[j * 3 + 1] = *(const uint4*)(AloB + ga);
                v[j * 3 + 2] = *(const uint4*)(BhiB + gb);
            }
        }

        const uint32_t base = sb + stage * QST;
        #pragma unroll
        for (int ks = 0; ks < 2; ks++) {
            uint32_t ahi[2][4], alo[2][4], bhi[8][2];
            #pragma unroll
            for (int mt = 0; mt < 2; mt++) {
                uint32_t r = a_r + mt * 16;
                uint32_t u = ks * 2 + a_u0;
                ldm4(ahi[mt], base + QOFF_AH + swz(r, u));
                if (lo_on) ldm4(alo[mt], base + QOFF_AL + swz(r, u));
            }
            #pragma unroll
            for (int p = 0; p < 4; p++) {
                uint32_t r = b_r + p * 16;
                uint32_t u = ks * 2 + b_u0;
                uint32_t t4[4];
                ldm4(t4, base + QOFF_BH + swz(r, u));
                bhi[2 * p][0] = t4[0]; bhi[2 * p][1] = t4[1];
                bhi[2 * p + 1][0] = t4[2]; bhi[2 * p + 1][1] = t4[3];
            }
            #pragma unroll
            for (int mt = 0; mt < 2; mt++)
                #pragma unroll
                for (int nt = 0; nt < 8; nt++)
                    mma_f16(c[mt][nt], ahi[mt], bhi[nt]);
            if (lo_on) {
                #pragma unroll
                for (int mt = 0; mt < 2; mt++)
                    #pragma unroll
                    for (int nt = 0; nt < 8; nt++)
                        mma_f16(c[mt][nt], alo[mt], bhi[nt]);
            }
        }

        if (kc < 11) {
            char* dst = sm + (stage ^ 1) * QST;
            #pragma unroll
            for (int j = 0; j < 2; j++) {
                int r = lr + j * 64;
                *(uint4*)(dst + QOFF_AH + swz(r, lu)) = v[j * 3 + 0];
                *(uint4*)(dst + QOFF_AL + swz(r, lu)) = v[j * 3 + 1];
                *(uint4*)(dst + QOFF_BH + swz(r, lu)) = v[j * 3 + 2];
            }
        }
        __syncthreads();
        stage ^= 1;
    }

    const int row0 = lane >> 2;
    const int col0 = (lane & 3) * 2;

    if (MODE == 0) {
        const int z = n0 / 384;
        const int nloc = n0 % 384;
        const float scl = (z == 0) ? 0.125f : 1.0f;
        __half* dhi = (z == 0) ? g_qhi : (z == 1) ? g_khi : g_vhi;
        #pragma unroll
        for (int mt = 0; mt < 2; mt++)
            #pragma unroll
            for (int half = 0; half < 2; half++) {
                int m = m0 + wm + mt * 16 + row0 + half * 8;
                int b = m >> 8, t = m & 255;
                #pragma unroll
                for (int nt = 0; nt < 8; nt++) {
                    int n = nloc + wn + nt * 8 + col0;
                    int h = n >> 6, d = n & 63;
                    size_t idx = (((size_t)b * HH + h) * TT + t) * DD + d;
                    float v0 = c[mt][nt][half * 2] * scl;
                    float v1 = c[mt][nt][half * 2 + 1] * scl;
                    uint32_t hp = pack_h2(v0, v1);
                    *(uint32_t*)(dhi + idx) = hp;
                    if (z == 0)
                        *(uint32_t*)(g_qlo + idx) = resid_h2(hp, v0, v1);
                }
            }
    } else {
        #pragma unroll
        for (int mt = 0; mt < 2; mt++)
            #pragma unroll
            for (int half = 0; half < 2; half++) {
                int m = m0 + wm + mt * 16 + row0 + half * 8;
                #pragma unroll
                for (int nt = 0; nt < 8; nt++) {
                    int n = n0 + wn + nt * 8 + col0;
                    float2 val = make_float2(c[mt][nt][half * 2] + bias[n],
                                             c[mt][nt][half * 2 + 1] + bias[n + 1]);
                    *(float2*)(outp + (size_t)m * EMB + n) = val;
                }
            }
    }
}

// ---------------------------------------------------------------------------
// fp16 flash attention, 2-term — exact R7-proven version.
// ---------------------------------------------------------------------------
#define AQHI 0
#define AQLO 16384
#define AKV0 32768
#define ATT_SMEM 98304

__global__ __launch_bounds__(256) void attn_tc()
{
    extern __shared__ char sm[];
    const uint32_t sb = smem_u32(sm);
    const int qt  = blockIdx.x;
    const int bh  = blockIdx.y;
    const int tid = threadIdx.x;
    const int wid = tid >> 5;
    const int lane = tid & 31;

    const __half* qhi = g_qhi + ((size_t)bh * TT + qt * 128) * DD;
    const __half* qlo = g_qlo + ((size_t)bh * TT + qt * 128) * DD;
    const __half* khi = g_khi + (size_t)bh * TT * DD;
    const __half* vhi = g_vhi + (size_t)bh * TT * DD;

    #pragma unroll
    for (int j = 0; j < 8; j++) {
        int idx = tid + 256 * j;
        int arr = idx >> 10;
        int r = (idx >> 3) & 127;
        int u = idx & 7;
        const __half* src = arr ? qlo : qhi;
        cp16(sb + (arr ? AQLO : AQHI) + swz8(r, u), src + (size_t)r * DD + u * 8);
    }
    #pragma unroll
    for (int j = 0; j < 8; j++) {
        int idx = tid + 256 * j;
        int arr = idx >> 10;
        int r = (idx >> 3) & 127;
        int u = idx & 7;
        const __half* src = arr ? vhi : khi;
        cp16(sb + AKV0 + arr * 16384 + swz8(r, u), src + (size_t)r * DD + u * 8);
    }
    CP_COMMIT();
    CP_WAIT_ALL();
    __syncthreads();

    uint32_t qfh[4][4], qfl[4][4];
    {
        int ar = wid * 16 + (lane & 15);
        #pragma unroll
        for (int kc = 0; kc < 4; kc++) {
            int u = kc * 2 + (lane >> 4);
            ldm4(qfh[kc], sb + AQHI + swz8(ar, u));
            ldm4(qfl[kc], sb + AQLO + swz8(ar, u));
        }
    }

    float o[8][4];
    #pragma unroll
    for (int nt = 0; nt < 8; nt++)
        #pragma unroll
        for (int q = 0; q < 4; q++) o[nt][q] = 0.0f;
    float mx[2] = {-1e30f, -1e30f};
    float lsum[2] = {0.0f, 0.0f};

    for (int kt = 0; kt <= qt; kt++) {
        const uint32_t kvb = sb + AKV0 + (kt & 1) * 32768;

        if (kt < qt) {
            #pragma unroll
            for (int j = 0; j < 8; j++) {
                int idx = tid + 256 * j;
                int arr = idx >> 10;
                int r = (idx >> 3) & 127;
                int u = idx & 7;
                const __half* src = arr ? vhi : khi;
                cp16(sb + AKV0 + ((kt + 1) & 1) * 32768 + arr * 16384 + swz8(r, u),
                     src + ((size_t)(kt + 1) * 128 + r) * DD + u * 8);
            }
            CP_COMMIT();
        }

        float s[16][4];
        #pragma unroll
        for (int nt = 0; nt < 16; nt++)
            #pragma unroll
            for (int q = 0; q < 4; q++) s[nt][q] = 0.0f;

        #pragma unroll
        for (int np = 0; np < 8; np++) {
            int br = np * 16 + ((lane >> 4) & 1) * 8 + (lane & 7);
            #pragma unroll
            for (int kc = 0; kc < 4; kc++) {
                int u = kc * 2 + ((lane >> 3) & 1);
                uint32_t th[4];
                ldm4(th, kvb + swz8(br, u));
                uint32_t b0h[2] = {th[0], th[1]}, b1h[2] = {th[2], th[3]};
                mma_f16(s[2 * np], qfh[kc], b0h);
                mma_f16(s[2 * np], qfl[kc], b0h);
                mma_f16(s[2 * np + 1], qfh[kc], b1h);
                mma_f16(s[2 * np + 1], qfl[kc], b1h);
            }
        }

        if (kt == qt) {
            #pragma unroll
            for (int nt = 0; nt < 16; nt++)
                #pragma unroll
                for (int q = 0; q < 4; q++) {
                    int col = nt * 8 + (lane & 3) * 2 + (q & 1);
                    int row = wid * 16 + (lane >> 2) + (q >> 1) * 8;
                    if (col > row) s[nt][q] = -1e30f;
                }
        }

        float al[2];
        #pragma unroll
        for (int hf = 0; hf < 2; hf++) {
            float rm = -1e30f;
            #pragma unroll
            for (int nt = 0; nt < 16; nt++)
                rm = fmaxf(rm, fmaxf(s[nt][hf * 2], s[nt][hf * 2 + 1]));
            rm = fmaxf(rm, __shfl_xor_sync(0xffffffffu, rm, 1));
            rm = fmaxf(rm, __shfl_xor_sync(0xffffffffu, rm, 2));
            float mn = fmaxf(mx[hf], rm);
            al[hf] = __expf(mx[hf] - mn);
            mx[hf] = mn;
            float ps = 0.0f;
            #pragma unroll
            for (int nt = 0; nt < 16; nt++) {
                s[nt][hf * 2]     = __expf(s[nt][hf * 2] - mn);
                s[nt][hf * 2 + 1] = __expf(s[nt][hf * 2 + 1] - mn);
                ps += s[nt][hf * 2] + s[nt][hf * 2 + 1];
            }
            ps += __shfl_xor_sync(0xffffffffu, ps, 1);
            ps += __shfl_xor_sync(0xffffffffu, ps, 2);
            lsum[hf] = lsum[hf] * al[hf] + ps;
        }
        #pragma unroll
        for (int nt = 0; nt < 8; nt++) {
            o[nt][0] *= al[0]; o[nt][1] *= al[0];
            o[nt][2] *= al[1]; o[nt][3] *= al[1];
        }

        #pragma unroll
        for (int kc = 0; kc < 8; kc++) {
            uint32_t ah[4], al4[4];
            ah[0] = pack_h2(s[2 * kc][0], s[2 * kc][1]);
            ah[1] = pack_h2(s[2 * kc][2], s[2 * kc][3]);
            ah[2] = pack_h2(s[2 * kc + 1][0], s[2 * kc + 1][1]);
            ah[3] = pack_h2(s[2 * kc + 1][2], s[2 * kc + 1][3]);
            al4[0] = resid_h2(ah[0], s[2 * kc][0], s[2 * kc][1]);
            al4[1] = resid_h2(ah[1], s[2 * kc][2], s[2 * kc][3]);
            al4[2] = resid_h2(ah[2], s[2 * kc + 1][0], s[2 * kc + 1][1]);
            al4[3] = resid_h2(ah[3], s[2 * kc + 1][2], s[2 * kc + 1][3]);

            int vr = kc * 16 + ((lane >> 3) & 1) * 8 + (lane & 7);
            #pragma unroll
            for (int ntp = 0; ntp < 4; ntp++) {
                int u = ntp * 2 + (lane >> 4);
                uint32_t th[4];
                ldm4t(th, kvb + 16384 + swz8(vr, u));
                uint32_t b0h[2] = {th[0], th[1]}, b1h[2] = {th[2], th[3]};
                mma_f16(o[2 * ntp], ah, b0h);
                mma_f16(o[2 * ntp], al4, b0h);
                mma_f16(o[2 * ntp + 1], ah, b1h);
                mma_f16(o[2 * ntp + 1], al4, b1h);
            }
        }

        if (kt < qt) {
            CP_WAIT_ALL();
            __syncthreads();
        }
    }

    const int b = bh / HH, h = bh % HH;
    #pragma unroll
    for (int hf = 0; hf < 2; hf++) {
        float inv = 1.0f / lsum[hf];
        int t = qt * 128 + wid * 16 + (lane >> 2) + hf * 8;
        size_t rowb = ((size_t)b * TT + t) * EMB + h * 64 + (lane & 3) * 2;
        #pragma unroll
        for (int nt = 0; nt < 8; nt++) {
            float v0 = o[nt][hf * 2] * inv;
            float v1 = o[nt][hf * 2 + 1] * inv;
            uint32_t hp = pack_h2(v0, v1);
            *(uint32_t*)(g_atthi + rowb + nt * 8) = hp;
            *(uint32_t*)(g_attlo + rowb + nt * 8) = resid_h2(hp, v0, v1);
        }
    }
}

// ---------------------------------------------------------------------------
extern "C" void kernel_launch(void* const* d_in, const int* in_sizes, int n_in,
                              void* d_out, int out_size)
{
    const float* x      = (const float*)d_in[0];
    const float* wq     = (const float*)d_in[1];
    const float* wk     = (const float*)d_in[2];
    const float* wv     = (const float*)d_in[3];
    const float* w_proj = (const float*)d_in[4];
    const float* b_proj = (const float*)d_in[5];
    float* out = (float*)d_out;

    cudaFuncSetAttribute(gemm_f16<0>, cudaFuncAttributeMaxDynamicSharedMemorySize, 2 * QST);
    cudaFuncSetAttribute(gemm_f16<1>, cudaFuncAttributeMaxDynamicSharedMemorySize, 2 * QST);
    cudaFuncSetAttribute(attn_tc, cudaFuncAttributeMaxDynamicSharedMemorySize, ATT_SMEM);

    prep_x<<<(BT * EMB + 255) / 256, 256>>>(x);
    prep_w<<<(3 * HH * DD * EMB + 255) / 256, 256>>>(wq, wk, wv);
    prep_wp<<<(EMB * EMB + 255) / 256, 256>>>(w_proj);

    gemm_f16<0><<<dim3(1152 / 128, BT / 128), 256, 2 * QST>>>(nullptr, nullptr);
    attn_tc<<<dim3(TT / 128, BB * HH), 256, ATT_SMEM>>>();
    gemm_f16<1><<<dim3(EMB / 128, BT / 128), 256, 2 * QST>>>(b_proj, out);
}

// round 10
// speedup vs baseline: 1.3673x; 1.1330x over previous
#include <cuda_runtime.h>
#include <cuda_bf16.h>
#include <cuda_fp16.h>
#include <cstdint>

#define BB 256
#define TT 256
#define EMB 384
#define HH 6
#define DD 64
#define BT (BB*TT)

// ---------------------------------------------------------------------------
// Scratch (__device__ globals — allocation-free rule).  All fp16.
// ---------------------------------------------------------------------------
__device__ __align__(16) __half g_qhi[BB * HH * TT * DD];
__device__ __align__(16) __half g_qlo[BB * HH * TT * DD];
__device__ __align__(16) __half g_khi[BB * HH * TT * DD];   // hi only
__device__ __align__(16) __half g_vhi[BB * HH * TT * DD];   // hi only
__device__ __align__(16) __half g_xhi[BT * EMB];
__device__ __align__(16) __half g_xlo[BT * EMB];
__device__ __align__(16) __half g_wthi[3 * HH * DD * EMB];  // [n=z*384+h*64+d][e]
__device__ __align__(16) __half g_wphi[EMB * EMB];          // [n][k]
__device__ __align__(16) __half g_atthi[BT * EMB];          // hi only now

// ---------------------------------------------------------------------------
// mma.sync / ldmatrix / cp.async helpers
// ---------------------------------------------------------------------------
__device__ __forceinline__ uint32_t smem_u32(const void* p) {
    uint32_t a;
    asm("{ .reg .u64 t; cvta.to.shared.u64 t, %1; cvt.u32.u64 %0, t; }"
        : "=r"(a) : "l"(p));
    return a;
}
__device__ __forceinline__ void ldm4(uint32_t* r, uint32_t addr) {
    asm volatile("ldmatrix.sync.aligned.m8n8.x4.shared.b16 {%0,%1,%2,%3}, [%4];"
        : "=r"(r[0]), "=r"(r[1]), "=r"(r[2]), "=r"(r[3]) : "r"(addr));
}
__device__ __forceinline__ void ldm4t(uint32_t* r, uint32_t addr) {
    asm volatile("ldmatrix.sync.aligned.m8n8.x4.trans.shared.b16 {%0,%1,%2,%3}, [%4];"
        : "=r"(r[0]), "=r"(r[1]), "=r"(r[2]), "=r"(r[3]) : "r"(addr));
}
__device__ __forceinline__ void mma_f16(float* c, const uint32_t* a, const uint32_t* b) {
    asm volatile(
        "mma.sync.aligned.m16n8k16.row.col.f32.f16.f16.f32 "
        "{%0,%1,%2,%3}, {%4,%5,%6,%7}, {%8,%9}, {%0,%1,%2,%3};"
        : "+f"(c[0]), "+f"(c[1]), "+f"(c[2]), "+f"(c[3])
        : "r"(a[0]), "r"(a[1]), "r"(a[2]), "r"(a[3]), "r"(b[0]), "r"(b[1]));
}
__device__ __forceinline__ void cp16(uint32_t dst, const void* src) {
    asm volatile("cp.async.cg.shared.global [%0], [%1], 16;" :: "r"(dst), "l"(src));
}
#define CP_COMMIT() asm volatile("cp.async.commit_group;" ::: "memory")
#define CP_WAIT_ALL() asm volatile("cp.async.wait_group 0;" ::: "memory")

__device__ __forceinline__ uint32_t pack_h2(float lo, float hi) {
    __half2 h = __floats2half2_rn(lo, hi);
    return *(uint32_t*)&h;
}
__device__ __forceinline__ uint32_t resid_h2(uint32_t u, float lo, float hi) {
    __half2 h = *(__half2*)&u;
    float2 f = __half22float2(h);
    return pack_h2(lo - f.x, hi - f.y);
}

// 64B-row tile swizzle (4 units of 16B): u ^ ((r>>1)&3)
__device__ __forceinline__ uint32_t swz(uint32_t r, uint32_t u) {
    return (r << 6) + ((u ^ ((r >> 1) & 3u)) << 4);
}
// 128B-row tile swizzle (8 units of 16B): u ^ (r&7)
__device__ __forceinline__ uint32_t swz8(uint32_t r, uint32_t u) {
    return (r << 7) + ((u ^ (r & 7u)) << 4);
}

// ---------------------------------------------------------------------------
// Prep kernels
// ---------------------------------------------------------------------------
__global__ void prep_x(const float* __restrict__ x) {
    int i = blockIdx.x * 256 + threadIdx.x;
    if (i < BT * EMB) {
        float v = x[i];
        __half h = __float2half(v);
        g_xhi[i] = h;
        g_xlo[i] = __float2half(v - __half2float(h));
    }
}
__global__ void prep_w(const float* __restrict__ wq, const float* __restrict__ wk,
                       const float* __restrict__ wv) {
    int i = blockIdx.x * 256 + threadIdx.x;
    if (i >= 3 * HH * DD * EMB) return;
    int e = i % EMB;
    int d = (i / EMB) % DD;
    int h = (i / (EMB * DD)) % HH;
    int z = i / (EMB * DD * HH);
    const float* w = (z == 0) ? wq : (z == 1) ? wk : wv;
    g_wthi[i] = __float2half(w[(h * EMB + e) * DD + d]);
}
__global__ void prep_wp(const float* __restrict__ wp) {
    int i = blockIdx.x * 256 + threadIdx.x;
    if (i >= EMB * EMB) return;
    int k = i % EMB;
    int n = i / EMB;
    g_wphi[i] = __float2half(wp[k * EMB + n]);
}

// ---------------------------------------------------------------------------
// fp16 GEMM.  C[M,N] = A[M,384] x B[384,N].
// MODE 0: qkv — 2-term only on Q tiles (n0<384); K/V tiles skip ALL lo work
//         (loads, STS, ldmatrix, MMAs).
// MODE 1: proj — 1-term (A = att hi, already fp16-rounded); bias; fp32 out.
// ---------------------------------------------------------------------------
#define QST 24576
#define QOFF_AH 0
#define QOFF_AL 8192
#define QOFF_BH 16384

template<int MODE>
__global__ __launch_bounds__(256, 2) void gemm_f16(const float* __restrict__ bias,
                                                   float* __restrict__ outp)
{
    extern __shared__ char sm[];
    const uint32_t sb = smem_u32(sm);

    const char* AhiB = (const char*)(MODE == 0 ? g_xhi : g_atthi);
    const char* AloB = (const char*)g_xlo;       // only used when lo_on
    const char* BhiB = (const char*)(MODE == 0 ? g_wthi : g_wphi);

    const int tid  = threadIdx.x;
    const int wid  = tid >> 5;
    const int lane = tid & 31;
    const int m0   = blockIdx.y * 128;
    const int n0   = blockIdx.x * 128;

    // lo-term only for qkv Q tiles
    const bool lo_on = (MODE == 0) && (n0 < 384);

    const int lr = tid >> 2;
    const int lu = tid & 3;

    const int wm   = (wid >> 1) * 32;
    const int wn   = (wid & 1) * 64;
    const int a_r  = wm + (lane & 15);
    const int a_u0 = (lane >> 4);
    const int b_r  = wn + ((lane >> 4) & 1) * 8 + (lane & 7);
    const int b_u0 = (lane >> 3) & 1;

    float c[2][8][4];
    #pragma unroll
    for (int mt = 0; mt < 2; mt++)
        #pragma unroll
        for (int nt = 0; nt < 8; nt++)
            #pragma unroll
            for (int q = 0; q < 4; q++) c[mt][nt][q] = 0.0f;

    {
        #pragma unroll
        for (int j = 0; j < 2; j++) {
            int r = lr + j * 64;
            size_t ga = (size_t)(m0 + r) * 768 + lu * 16;
            size_t gb = (size_t)(n0 + r) * 768 + lu * 16;
            *(uint4*)(sm + QOFF_AH + swz(r, lu)) = *(const uint4*)(AhiB + ga);
            if (lo_on)
                *(uint4*)(sm + QOFF_AL + swz(r, lu)) = *(const uint4*)(AloB + ga);
            *(uint4*)(sm + QOFF_BH + swz(r, lu)) = *(const uint4*)(BhiB + gb);
        }
    }
    __syncthreads();

    int stage = 0;
    for (int kc = 0; kc < 12; kc++) {
        uint4 v[6];
        if (kc < 11) {
            const int ko = (kc + 1) * 64;
            #pragma unroll
            for (int j = 0; j < 2; j++) {
                int r = lr + j * 64;
                size_t ga = (size_t)(m0 + r) * 768 + ko + lu * 16;
                size_t gb = (size_t)(n0 + r) * 768 + ko + lu * 16;
                v[j * 3 + 0] = *(const uint4*)(AhiB + ga);
                if (lo_on) v[j * 3 + 1] = *(const uint4*)(AloB + ga);
                v[j * 3 + 2] = *(const uint4*)(BhiB + gb);
            }
        }

        const uint32_t base = sb + stage * QST;
        #pragma unroll
        for (int ks = 0; ks < 2; ks++) {
            uint32_t ahi[2][4], alo[2][4], bhi[8][2];
            #pragma unroll
            for (int mt = 0; mt < 2; mt++) {
                uint32_t r = a_r + mt * 16;
                uint32_t u = ks * 2 + a_u0;
                ldm4(ahi[mt], base + QOFF_AH + swz(r, u));
                if (lo_on) ldm4(alo[mt], base + QOFF_AL + swz(r, u));
            }
            #pragma unroll
            for (int p = 0; p < 4; p++) {
                uint32_t r = b_r + p * 16;
                uint32_t u = ks * 2 + b_u0;
                uint32_t t4[4];
                ldm4(t4, base + QOFF_BH + swz(r, u));
                bhi[2 * p][0] = t4[0]; bhi[2 * p][1] = t4[1];
                bhi[2 * p + 1][0] = t4[2]; bhi[2 * p + 1][1] = t4[3];
            }
            #pragma unroll
            for (int mt = 0; mt < 2; mt++)
                #pragma unroll
                for (int nt = 0; nt < 8; nt++)
                    mma_f16(c[mt][nt], ahi[mt], bhi[nt]);
            if (lo_on) {
                #pragma unroll
                for (int mt = 0; mt < 2; mt++)
                    #pragma unroll
                    for (int nt = 0; nt < 8; nt++)
                        mma_f16(c[mt][nt], alo[mt], bhi[nt]);
            }
        }

        if (kc < 11) {
            char* dst = sm + (stage ^ 1) * QST;
            #pragma unroll
            for (int j = 0; j < 2; j++) {
                int r = lr + j * 64;
                *(uint4*)(dst + QOFF_AH + swz(r, lu)) = v[j * 3 + 0];
                if (lo_on) *(uint4*)(dst + QOFF_AL + swz(r, lu)) = v[j * 3 + 1];
                *(uint4*)(dst + QOFF_BH + swz(r, lu)) = v[j * 3 + 2];
            }
        }
        __syncthreads();
        stage ^= 1;
    }

    const int row0 = lane >> 2;
    const int col0 = (lane & 3) * 2;

    if (MODE == 0) {
        const int z = n0 / 384;
        const int nloc = n0 % 384;
        const float scl = (z == 0) ? 0.125f : 1.0f;
        __half* dhi = (z == 0) ? g_qhi : (z == 1) ? g_khi : g_vhi;
        #pragma unroll
        for (int mt = 0; mt < 2; mt++)
            #pragma unroll
            for (int half = 0; half < 2; half++) {
                int m = m0 + wm + mt * 16 + row0 + half * 8;
                int b = m >> 8, t = m & 255;
                #pragma unroll
                for (int nt = 0; nt < 8; nt++) {
                    int n = nloc + wn + nt * 8 + col0;
                    int h = n >> 6, d = n & 63;
                    size_t idx = (((size_t)b * HH + h) * TT + t) * DD + d;
                    float v0 = c[mt][nt][half * 2] * scl;
                    float v1 = c[mt][nt][half * 2 + 1] * scl;
                    uint32_t hp = pack_h2(v0, v1);
                    *(uint32_t*)(dhi + idx) = hp;
                    if (z == 0)
                        *(uint32_t*)(g_qlo + idx) = resid_h2(hp, v0, v1);
                }
            }
    } else {
        #pragma unroll
        for (int mt = 0; mt < 2; mt++)
            #pragma unroll
            for (int half = 0; half < 2; half++) {
                int m = m0 + wm + mt * 16 + row0 + half * 8;
                #pragma unroll
                for (int nt = 0; nt < 8; nt++) {
                    int n = n0 + wn + nt * 8 + col0;
                    float2 val = make_float2(c[mt][nt][half * 2] + bias[n],
                                             c[mt][nt][half * 2 + 1] + bias[n + 1]);
                    *(float2*)(outp + (size_t)m * EMB + n) = val;
                }
            }
    }
}

// ---------------------------------------------------------------------------
// fp16 flash attention, 2-term — R7/R9-proven; epilogue now hi-only.
// ---------------------------------------------------------------------------
#define AQHI 0
#define AQLO 16384
#define AKV0 32768
#define ATT_SMEM 98304

__global__ __launch_bounds__(256) void attn_tc()
{
    extern __shared__ char sm[];
    const uint32_t sb = smem_u32(sm);
    const int qt  = blockIdx.x;
    const int bh  = blockIdx.y;
    const int tid = threadIdx.x;
    const int wid = tid >> 5;
    const int lane = tid & 31;

    const __half* qhi = g_qhi + ((size_t)bh * TT + qt * 128) * DD;
    const __half* qlo = g_qlo + ((size_t)bh * TT + qt * 128) * DD;
    const __half* khi = g_khi + (size_t)bh * TT * DD;
    const __half* vhi = g_vhi + (size_t)bh * TT * DD;

    #pragma unroll
    for (int j = 0; j < 8; j++) {
        int idx = tid + 256 * j;
        int arr = idx >> 10;
        int r = (idx >> 3) & 127;
        int u = idx & 7;
        const __half* src = arr ? qlo : qhi;
        cp16(sb + (arr ? AQLO : AQHI) + swz8(r, u), src + (size_t)r * DD + u * 8);
    }
    #pragma unroll
    for (int j = 0; j < 8; j++) {
        int idx = tid + 256 * j;
        int arr = idx >> 10;
        int r = (idx >> 3) & 127;
        int u = idx & 7;
        const __half* src = arr ? vhi : khi;
        cp16(sb + AKV0 + arr * 16384 + swz8(r, u), src + (size_t)r * DD + u * 8);
    }
    CP_COMMIT();
    CP_WAIT_ALL();
    __syncthreads();

    uint32_t qfh[4][4], qfl[4][4];
    {
        int ar = wid * 16 + (lane & 15);
        #pragma unroll
        for (int kc = 0; kc < 4; kc++) {
            int u = kc * 2 + (lane >> 4);
            ldm4(qfh[kc], sb + AQHI + swz8(ar, u));
            ldm4(qfl[kc], sb + AQLO + swz8(ar, u));
        }
    }

    float o[8][4];
    #pragma unroll
    for (int nt = 0; nt < 8; nt++)
        #pragma unroll
        for (int q = 0; q < 4; q++) o[nt][q] = 0.0f;
    float mx[2] = {-1e30f, -1e30f};
    float lsum[2] = {0.0f, 0.0f};

    for (int kt = 0; kt <= qt; kt++) {
        const uint32_t kvb = sb + AKV0 + (kt & 1) * 32768;

        if (kt < qt) {
            #pragma unroll
            for (int j = 0; j < 8; j++) {
                int idx = tid + 256 * j;
                int arr = idx >> 10;
                int r = (idx >> 3) & 127;
                int u = idx & 7;
                const __half* src = arr ? vhi : khi;
                cp16(sb + AKV0 + ((kt + 1) & 1) * 32768 + arr * 16384 + swz8(r, u),
                     src + ((size_t)(kt + 1) * 128 + r) * DD + u * 8);
            }
            CP_COMMIT();
        }

        float s[16][4];
        #pragma unroll
        for (int nt = 0; nt < 16; nt++)
            #pragma unroll
            for (int q = 0; q < 4; q++) s[nt][q] = 0.0f;

        #pragma unroll
        for (int np = 0; np < 8; np++) {
            int br = np * 16 + ((lane >> 4) & 1) * 8 + (lane & 7);
            #pragma unroll
            for (int kc = 0; kc < 4; kc++) {
                int u = kc * 2 + ((lane >> 3) & 1);
                uint32_t th[4];
                ldm4(th, kvb + swz8(br, u));
                uint32_t b0h[2] = {th[0], th[1]}, b1h[2] = {th[2], th[3]};
                mma_f16(s[2 * np], qfh[kc], b0h);
                mma_f16(s[2 * np], qfl[kc], b0h);
                mma_f16(s[2 * np + 1], qfh[kc], b1h);
                mma_f16(s[2 * np + 1], qfl[kc], b1h);
            }
        }

        if (kt == qt) {
            #pragma unroll
            for (int nt = 0; nt < 16; nt++)
                #pragma unroll
                for (int q = 0; q < 4; q++) {
                    int col = nt * 8 + (lane & 3) * 2 + (q & 1);
                    int row = wid * 16 + (lane >> 2) + (q >> 1) * 8;
                    if (col > row) s[nt][q] = -1e30f;
                }
        }

        float al[2];
        #pragma unroll
        for (int hf = 0; hf < 2; hf++) {
            float rm = -1e30f;
            #pragma unroll
            for (int nt = 0; nt < 16; nt++)
                rm = fmaxf(rm, fmaxf(s[nt][hf * 2], s[nt][hf * 2 + 1]));
            rm = fmaxf(rm, __shfl_xor_sync(0xffffffffu, rm, 1));
            rm = fmaxf(rm, __shfl_xor_sync(0xffffffffu, rm, 2));
            float mn = fmaxf(mx[hf], rm);
            al[hf] = __expf(mx[hf] - mn);
            mx[hf] = mn;
            float ps = 0.0f;
            #pragma unroll
            for (int nt = 0; nt < 16; nt++) {
                s[nt][hf * 2]     = __expf(s[nt][hf * 2] - mn);
                s[nt][hf * 2 + 1] = __expf(s[nt][hf * 2 + 1] - mn);
                ps += s[nt][hf * 2] + s[nt][hf * 2 + 1];
            }
            ps += __shfl_xor_sync(0xffffffffu, ps, 1);
            ps += __shfl_xor_sync(0xffffffffu, ps, 2);
            lsum[hf] = lsum[hf] * al[hf] + ps;
        }
        #pragma unroll
        for (int nt = 0; nt < 8; nt++) {
            o[nt][0] *= al[0]; o[nt][1] *= al[0];
            o[nt][2] *= al[1]; o[nt][3] *= al[1];
        }

        #pragma unroll
        for (int kc = 0; kc < 8; kc++) {
            uint32_t ah[4], al4[4];
            ah[0] = pack_h2(s[2 * kc][0], s[2 * kc][1]);
            ah[1] = pack_h2(s[2 * kc][2], s[2 * kc][3]);
            ah[2] = pack_h2(s[2 * kc + 1][0], s[2 * kc + 1][1]);
            ah[3] = pack_h2(s[2 * kc + 1][2], s[2 * kc + 1][3]);
            al4[0] = resid_h2(ah[0], s[2 * kc][0], s[2 * kc][1]);
            al4[1] = resid_h2(ah[1], s[2 * kc][2], s[2 * kc][3]);
            al4[2] = resid_h2(ah[2], s[2 * kc + 1][0], s[2 * kc + 1][1]);
            al4[3] = resid_h2(ah[3], s[2 * kc + 1][2], s[2 * kc + 1][3]);

            int vr = kc * 16 + ((lane >> 3) & 1) * 8 + (lane & 7);
            #pragma unroll
            for (int ntp = 0; ntp < 4; ntp++) {
                int u = ntp * 2 + (lane >> 4);
                uint32_t th[4];
                ldm4t(th, kvb + 16384 + swz8(vr, u));
                uint32_t b0h[2] = {th[0], th[1]}, b1h[2] = {th[2], th[3]};
                mma_f16(o[2 * ntp], ah, b0h);
                mma_f16(o[2 * ntp], al4, b0h);
                mma_f16(o[2 * ntp + 1], ah, b1h);
                mma_f16(o[2 * ntp + 1], al4, b1h);
            }
        }

        if (kt < qt) {
            CP_WAIT_ALL();
            __syncthreads();
        }
    }

    // epilogue: normalize, write fp16 hi-only att rows [BT][EMB]
    const int b = bh / HH, h = bh % HH;
    #pragma unroll
    for (int hf = 0; hf < 2; hf++) {
        float inv = 1.0f / lsum[hf];
        int t = qt * 128 + wid * 16 + (lane >> 2) + hf * 8;
        size_t rowb = ((size_t)b * TT + t) * EMB + h * 64 + (lane & 3) * 2;
        #pragma unroll
        for (int nt = 0; nt < 8; nt++) {
            float v0 = o[nt][hf * 2] * inv;
            float v1 = o[nt][hf * 2 + 1] * inv;
            *(uint32_t*)(g_atthi + rowb + nt * 8) = pack_h2(v0, v1);
        }
    }
}

// ---------------------------------------------------------------------------
extern "C" void kernel_launch(void* const* d_in, const int* in_sizes, int n_in,
                              void* d_out, int out_size)
{
    const float* x      = (const float*)d_in[0];
    const float* wq     = (const float*)d_in[1];
    const float* wk     = (const float*)d_in[2];
    const float* wv     = (const float*)d_in[3];
    const float* w_proj = (const float*)d_in[4];
    const float* b_proj = (const float*)d_in[5];
    float* out = (float*)d_out;

    cudaFuncSetAttribute(gemm_f16<0>, cudaFuncAttributeMaxDynamicSharedMemorySize, 2 * QST);
    cudaFuncSetAttribute(gemm_f16<1>, cudaFuncAttributeMaxDynamicSharedMemorySize, 2 * QST);
    cudaFuncSetAttribute(attn_tc, cudaFuncAttributeMaxDynamicSharedMemorySize, ATT_SMEM);

    prep_x<<<(BT * EMB + 255) / 256, 256>>>(x);
    prep_w<<<(3 * HH * DD * EMB + 255) / 256, 256>>>(wq, wk, wv);
    prep_wp<<<(EMB * EMB + 255) / 256, 256>>>(w_proj);

    gemm_f16<0><<<dim3(1152 / 128, BT / 128), 256, 2 * QST>>>(nullptr, nullptr);
    attn_tc<<<dim3(TT / 128, BB * HH), 256, ATT_SMEM>>>();
    gemm_f16<1><<<dim3(EMB / 128, BT / 128), 256, 2 * QST>>>(b_proj, out);
}

// round 11
// speedup vs baseline: 1.6380x; 1.1980x over previous
#include <cuda_runtime.h>
#include <cuda_bf16.h>
#include <cuda_fp16.h>
#include <cstdint>

#define BB 256
#define TT 256
#define EMB 384
#define HH 6
#define DD 64
#define BT (BB*TT)

// ---------------------------------------------------------------------------
// Scratch (__device__ globals — allocation-free rule).  Pure fp16 pipeline.
// ---------------------------------------------------------------------------
__device__ __align__(16) __half g_qhi[BB * HH * TT * DD];
__device__ __align__(16) __half g_khi[BB * HH * TT * DD];
__device__ __align__(16) __half g_vhi[BB * HH * TT * DD];
__device__ __align__(16) __half g_xhi[BT * EMB];
__device__ __align__(16) __half g_wthi[3 * HH * DD * EMB];  // [n=z*384+h*64+d][e]
__device__ __align__(16) __half g_wphi[EMB * EMB];          // [n][k]
__device__ __align__(16) __half g_atthi[BT * EMB];

// ---------------------------------------------------------------------------
// mma.sync / ldmatrix / cp.async helpers
// ---------------------------------------------------------------------------
__device__ __forceinline__ uint32_t smem_u32(const void* p) {
    uint32_t a;
    asm("{ .reg .u64 t; cvta.to.shared.u64 t, %1; cvt.u32.u64 %0, t; }"
        : "=r"(a) : "l"(p));
    return a;
}
__device__ __forceinline__ void ldm4(uint32_t* r, uint32_t addr) {
    asm volatile("ldmatrix.sync.aligned.m8n8.x4.shared.b16 {%0,%1,%2,%3}, [%4];"
        : "=r"(r[0]), "=r"(r[1]), "=r"(r[2]), "=r"(r[3]) : "r"(addr));
}
__device__ __forceinline__ void ldm4t(uint32_t* r, uint32_t addr) {
    asm volatile("ldmatrix.sync.aligned.m8n8.x4.trans.shared.b16 {%0,%1,%2,%3}, [%4];"
        : "=r"(r[0]), "=r"(r[1]), "=r"(r[2]), "=r"(r[3]) : "r"(addr));
}
__device__ __forceinline__ void mma_f16(float* c, const uint32_t* a, const uint32_t* b) {
    asm volatile(
        "mma.sync.aligned.m16n8k16.row.col.f32.f16.f16.f32 "
        "{%0,%1,%2,%3}, {%4,%5,%6,%7}, {%8,%9}, {%0,%1,%2,%3};"
        : "+f"(c[0]), "+f"(c[1]), "+f"(c[2]), "+f"(c[3])
        : "r"(a[0]), "r"(a[1]), "r"(a[2]), "r"(a[3]), "r"(b[0]), "r"(b[1]));
}
__device__ __forceinline__ void cp16(uint32_t dst, const void* src) {
    asm volatile("cp.async.cg.shared.global [%0], [%1], 16;" :: "r"(dst), "l"(src));
}
#define CP_COMMIT() asm volatile("cp.async.commit_group;" ::: "memory")
#define CP_WAIT_ALL() asm volatile("cp.async.wait_group 0;" ::: "memory")

__device__ __forceinline__ uint32_t pack_h2(float lo, float hi) {
    __half2 h = __floats2half2_rn(lo, hi);
    return *(uint32_t*)&h;
}
__device__ __forceinline__ uint32_t resid_h2(uint32_t u, float lo, float hi) {
    __half2 h = *(__half2*)&u;
    float2 f = __half22float2(h);
    return pack_h2(lo - f.x, hi - f.y);
}

// 64B-row tile swizzle (4 units of 16B): u ^ ((r>>1)&3)
__device__ __forceinline__ uint32_t swz(uint32_t r, uint32_t u) {
    return (r << 6) + ((u ^ ((r >> 1) & 3u)) << 4);
}
// 128B-row tile swizzle (8 units of 16B): u ^ (r&7)
__device__ __forceinline__ uint32_t swz8(uint32_t r, uint32_t u) {
    return (r << 7) + ((u ^ (r & 7u)) << 4);
}

// ---------------------------------------------------------------------------
// Single prep kernel: x -> fp16 hi; weights transposed -> fp16
// ---------------------------------------------------------------------------
#define NX  (BT * EMB)
#define NW1 (3 * HH * DD * EMB)
__global__ void prep_all(const float* __restrict__ x,
                         const float* __restrict__ wq, const float* __restrict__ wk,
                         const float* __restrict__ wv, const float* __restrict__ wp)
{
    int i = blockIdx.x * 256 + threadIdx.x;
    if (i < NX) {
        g_xhi[i] = __float2half(x[i]);
    } else if (i < NX + NW1) {
        int j = i - NX;
        int e = j % EMB;
        int d = (j / EMB) % DD;
        int h = (j / (EMB * DD)) % HH;
        int z = j / (EMB * DD * HH);
        const float* w = (z == 0) ? wq : (z == 1) ? wk : wv;
        g_wthi[j] = __float2half(w[(h * EMB + e) * DD + d]);
    } else if (i < NX + NW1 + EMB * EMB) {
        int j = i - NX - NW1;
        int k = j % EMB;
        int n = j / EMB;
        g_wphi[j] = __float2half(wp[k * EMB + n]);
    }
}

// ---------------------------------------------------------------------------
// Pure 1-term fp16 GEMM.  C[M,N] = A[M,384] x B[384,N].
// MODE 0: qkv (writes q/k/v fp16, q pre-scaled 1/8)
// MODE 1: proj (adds bias, writes fp32 out)
// Stage = Ahi(8KB) + Bhi(8KB) = 16KB; double-buffered = 32KB.
// ---------------------------------------------------------------------------
#define QST 16384
#define QOFF_AH 0
#define QOFF_BH 8192

template<int MODE>
__global__ __launch_bounds__(256, 2) void gemm_f16(const float* __restrict__ bias,
                                                   float* __restrict__ outp)
{
    extern __shared__ char sm[];
    const uint32_t sb = smem_u32(sm);

    const char* AhiB = (const char*)(MODE == 0 ? g_xhi : g_atthi);
    const char* BhiB = (const char*)(MODE == 0 ? g_wthi : g_wphi);

    const int tid  = threadIdx.x;
    const int wid  = tid >> 5;
    const int lane = tid & 31;
    const int m0   = blockIdx.y * 128;
    const int n0   = blockIdx.x * 128;

    const int lr = tid >> 2;
    const int lu = tid & 3;

    const int wm   = (wid >> 1) * 32;
    const int wn   = (wid & 1) * 64;
    const int a_r  = wm + (lane & 15);
    const int a_u0 = (lane >> 4);
    const int b_r  = wn + ((lane >> 4) & 1) * 8 + (lane & 7);
    const int b_u0 = (lane >> 3) & 1;

    float c[2][8][4];
    #pragma unroll
    for (int mt = 0; mt < 2; mt++)
        #pragma unroll
        for (int nt = 0; nt < 8; nt++)
            #pragma unroll
            for (int q = 0; q < 4; q++) c[mt][nt][q] = 0.0f;

    {
        #pragma unroll
        for (int j = 0; j < 2; j++) {
            int r = lr + j * 64;
            *(uint4*)(sm + QOFF_AH + swz(r, lu)) =
                *(const uint4*)(AhiB + (size_t)(m0 + r) * 768 + lu * 16);
            *(uint4*)(sm + QOFF_BH + swz(r, lu)) =
                *(const uint4*)(BhiB + (size_t)(n0 + r) * 768 + lu * 16);
        }
    }
    __syncthreads();

    int stage = 0;
    for (int kc = 0; kc < 12; kc++) {
        uint4 v[4];
        if (kc < 11) {
            const int ko = (kc + 1) * 64;
            #pragma unroll
            for (int j = 0; j < 2; j++) {
                int r = lr + j * 64;
                v[j * 2 + 0] = *(const uint4*)(AhiB + (size_t)(m0 + r) * 768 + ko + lu * 16);
                v[j * 2 + 1] = *(const uint4*)(BhiB + (size_t)(n0 + r) * 768 + ko + lu * 16);
            }
        }

        const uint32_t base = sb + stage * QST;
        #pragma unroll
        for (int ks = 0; ks < 2; ks++) {
            uint32_t ahi[2][4], bhi[8][2];
            #pragma unroll
            for (int mt = 0; mt < 2; mt++) {
                uint32_t r = a_r + mt * 16;
                uint32_t u = ks * 2 + a_u0;
                ldm4(ahi[mt], base + QOFF_AH + swz(r, u));
            }
            #pragma unroll
            for (int p = 0; p < 4; p++) {
                uint32_t r = b_r + p * 16;
                uint32_t u = ks * 2 + b_u0;
                uint32_t t4[4];
                ldm4(t4, base + QOFF_BH + swz(r, u));
                bhi[2 * p][0] = t4[0]; bhi[2 * p][1] = t4[1];
                bhi[2 * p + 1][0] = t4[2]; bhi[2 * p + 1][1] = t4[3];
            }
            #pragma unroll
            for (int mt = 0; mt < 2; mt++)
                #pragma unroll
                for (int nt = 0; nt < 8; nt++)
                    mma_f16(c[mt][nt], ahi[mt], bhi[nt]);
        }

        if (kc < 11) {
            char* dst = sm + (stage ^ 1) * QST;
            #pragma unroll
            for (int j = 0; j < 2; j++) {
                int r = lr + j * 64;
                *(uint4*)(dst + QOFF_AH + swz(r, lu)) = v[j * 2 + 0];
                *(uint4*)(dst + QOFF_BH + swz(r, lu)) = v[j * 2 + 1];
            }
        }
        __syncthreads();
        stage ^= 1;
    }

    const int row0 = lane >> 2;
    const int col0 = (lane & 3) * 2;

    if (MODE == 0) {
        const int z = n0 / 384;
        const int nloc = n0 % 384;
        const float scl = (z == 0) ? 0.125f : 1.0f;
        __half* dhi = (z == 0) ? g_qhi : (z == 1) ? g_khi : g_vhi;
        #pragma unroll
        for (int mt = 0; mt < 2; mt++)
            #pragma unroll
            for (int half = 0; half < 2; half++) {
                int m = m0 + wm + mt * 16 + row0 + half * 8;
                int b = m >> 8, t = m & 255;
                #pragma unroll
                for (int nt = 0; nt < 8; nt++) {
                    int n = nloc + wn + nt * 8 + col0;
                    int h = n >> 6, d = n & 63;
                    size_t idx = (((size_t)b * HH + h) * TT + t) * DD + d;
                    *(uint32_t*)(dhi + idx) =
                        pack_h2(c[mt][nt][half * 2] * scl, c[mt][nt][half * 2 + 1] * scl);
                }
            }
    } else {
        #pragma unroll
        for (int mt = 0; mt < 2; mt++)
            #pragma unroll
            for (int half = 0; half < 2; half++) {
                int m = m0 + wm + mt * 16 + row0 + half * 8;
                #pragma unroll
                for (int nt = 0; nt < 8; nt++) {
                    int n = n0 + wn + nt * 8 + col0;
                    float2 val = make_float2(c[mt][nt][half * 2] + bias[n],
                                             c[mt][nt][half * 2 + 1] + bias[n + 1]);
                    *(float2*)(outp + (size_t)m * EMB + n) = val;
                }
            }
    }
}

// ---------------------------------------------------------------------------
// fp16 flash attention: S 1-term (Qh.Kh), PV 2-term (P-residual is free).
// smem: Q 16KB + 2 stages x (K 16KB + V 16KB) = 80KB.
// ---------------------------------------------------------------------------
#define AQHI 0
#define AKV0 16384
#define ATT_SMEM 81920

__global__ __launch_bounds__(256) void attn_tc()
{
    extern __shared__ char sm[];
    const uint32_t sb = smem_u32(sm);
    const int qt  = blockIdx.x;
    const int bh  = blockIdx.y;
    const int tid = threadIdx.x;
    const int wid = tid >> 5;
    const int lane = tid & 31;

    const __half* qhi = g_qhi + ((size_t)bh * TT + qt * 128) * DD;
    const __half* khi = g_khi + (size_t)bh * TT * DD;
    const __half* vhi = g_vhi + (size_t)bh * TT * DD;

    // Q hi (1024 units) + K/V tile 0 (2048 units) via cp.async
    #pragma unroll
    for (int j = 0; j < 4; j++) {
        int idx = tid + 256 * j;
        int r = idx >> 3;
        int u = idx & 7;
        cp16(sb + AQHI + swz8(r, u), qhi + (size_t)r * DD + u * 8);
    }
    #pragma unroll
    for (int j = 0; j < 8; j++) {
        int idx = tid + 256 * j;
        int arr = idx >> 10;                  // 0 = K, 1 = V
        int r = (idx >> 3) & 127;
        int u = idx & 7;
        const __half* src = arr ? vhi : khi;
        cp16(sb + AKV0 + arr * 16384 + swz8(r, u), src + (size_t)r * DD + u * 8);
    }
    CP_COMMIT();
    CP_WAIT_ALL();
    __syncthreads();

    uint32_t qfh[4][4];
    {
        int ar = wid * 16 + (lane & 15);
        #pragma unroll
        for (int kc = 0; kc < 4; kc++) {
            int u = kc * 2 + (lane >> 4);
            ldm4(qfh[kc], sb + AQHI + swz8(ar, u));
        }
    }

    float o[8][4];
    #pragma unroll
    for (int nt = 0; nt < 8; nt++)
        #pragma unroll
        for (int q = 0; q < 4; q++) o[nt][q] = 0.0f;
    float mx[2] = {-1e30f, -1e30f};
    float lsum[2] = {0.0f, 0.0f};

    for (int kt = 0; kt <= qt; kt++) {
        const uint32_t kvb = sb + AKV0 + (kt & 1) * 32768;

        if (kt < qt) {
            #pragma unroll
            for (int j = 0; j < 8; j++) {
                int idx = tid + 256 * j;
                int arr = idx >> 10;
                int r = (idx >> 3) & 127;
                int u = idx & 7;
                const __half* src = arr ? vhi : khi;
                cp16(sb + AKV0 + ((kt + 1) & 1) * 32768 + arr * 16384 + swz8(r, u),
                     src + ((size_t)(kt + 1) * 128 + r) * DD + u * 8);
            }
            CP_COMMIT();
        }

        // S = Qh Kh^T (1-term)
        float s[16][4];
        #pragma unroll
        for (int nt = 0; nt < 16; nt++)
            #pragma unroll
            for (int q = 0; q < 4; q++) s[nt][q] = 0.0f;

        #pragma unroll
        for (int np = 0; np < 8; np++) {
            int br = np * 16 + ((lane >> 4) & 1) * 8 + (lane & 7);
            #pragma unroll
            for (int kc = 0; kc < 4; kc++) {
                int u = kc * 2 + ((lane >> 3) & 1);
                uint32_t th[4];
                ldm4(th, kvb + swz8(br, u));
                uint32_t b0h[2] = {th[0], th[1]}, b1h[2] = {th[2], th[3]};
                mma_f16(s[2 * np], qfh[kc], b0h);
                mma_f16(s[2 * np + 1], qfh[kc], b1h);
            }
        }

        if (kt == qt) {
            #pragma unroll
            for (int nt = 0; nt < 16; nt++)
                #pragma unroll
                for (int q = 0; q < 4; q++) {
                    int col = nt * 8 + (lane & 3) * 2 + (q & 1);
                    int row = wid * 16 + (lane >> 2) + (q >> 1) * 8;
                    if (col > row) s[nt][q] = -1e30f;
                }
        }

        float al[2];
        #pragma unroll
        for (int hf = 0; hf < 2; hf++) {
            float rm = -1e30f;
            #pragma unroll
            for (int nt = 0; nt < 16; nt++)
                rm = fmaxf(rm, fmaxf(s[nt][hf * 2], s[nt][hf * 2 + 1]));
            rm = fmaxf(rm, __shfl_xor_sync(0xffffffffu, rm, 1));
            rm = fmaxf(rm, __shfl_xor_sync(0xffffffffu, rm, 2));
            float mn = fmaxf(mx[hf], rm);
            al[hf] = __expf(mx[hf] - mn);
            mx[hf] = mn;
            float ps = 0.0f;
            #pragma unroll
            for (int nt = 0; nt < 16; nt++) {
                s[nt][hf * 2]     = __expf(s[nt][hf * 2] - mn);
                s[nt][hf * 2 + 1] = __expf(s[nt][hf * 2 + 1] - mn);
                ps += s[nt][hf * 2] + s[nt][hf * 2 + 1];
            }
            ps += __shfl_xor_sync(0xffffffffu, ps, 1);
            ps += __shfl_xor_sync(0xffffffffu, ps, 2);
            lsum[hf] = lsum[hf] * al[hf] + ps;
        }
        #pragma unroll
        for (int nt = 0; nt < 8; nt++) {
            o[nt][0] *= al[0]; o[nt][1] *= al[0];
            o[nt][2] *= al[1]; o[nt][3] *= al[1];
        }

        // O += P V (2-term: P hi + residual)
        #pragma unroll
        for (int kc = 0; kc < 8; kc++) {
            uint32_t ah[4], al4[4];
            ah[0] = pack_h2(s[2 * kc][0], s[2 * kc][1]);
            ah[1] = pack_h2(s[2 * kc][2], s[2 * kc][3]);
            ah[2] = pack_h2(s[2 * kc + 1][0], s[2 * kc + 1][1]);
            ah[3] = pack_h2(s[2 * kc + 1][2], s[2 * kc + 1][3]);
            al4[0] = resid_h2(ah[0], s[2 * kc][0], s[2 * kc][1]);
            al4[1] = resid_h2(ah[1], s[2 * kc][2], s[2 * kc][3]);
            al4[2] = resid_h2(ah[2], s[2 * kc + 1][0], s[2 * kc + 1][1]);
            al4[3] = resid_h2(ah[3], s[2 * kc + 1][2], s[2 * kc + 1][3]);

            int vr = kc * 16 + ((lane >> 3) & 1) * 8 + (lane & 7);
            #pragma unroll
            for (int ntp = 0; ntp < 4; ntp++) {
                int u = ntp * 2 + (lane >> 4);
                uint32_t th[4];
                ldm4t(th, kvb + 16384 + swz8(vr, u));
                uint32_t b0h[2] = {th[0], th[1]}, b1h[2] = {th[2], th[3]};
                mma_f16(o[2 * ntp], ah, b0h);
                mma_f16(o[2 * ntp], al4, b0h);
                mma_f16(o[2 * ntp + 1], ah, b1h);
                mma_f16(o[2 * ntp + 1], al4, b1h);
            }
        }

        if (kt < qt) {
            CP_WAIT_ALL();
            __syncthreads();
        }
    }

    // epilogue: normalize, write fp16 att rows [BT][EMB]
    const int b = bh / HH, h = bh % HH;
    #pragma unroll
    for (int hf = 0; hf < 2; hf++) {
        float inv = 1.0f / lsum[hf];
        int t = qt * 128 + wid * 16 + (lane >> 2) + hf * 8;
        size_t rowb = ((size_t)b * TT + t) * EMB + h * 64 + (lane & 3) * 2;
        #pragma unroll
        for (int nt = 0; nt < 8; nt++)
            *(uint32_t*)(g_atthi + rowb + nt * 8) =
                pack_h2(o[nt][hf * 2] * inv, o[nt][hf * 2 + 1] * inv);
    }
}

// ---------------------------------------------------------------------------
extern "C" void kernel_launch(void* const* d_in, const int* in_sizes, int n_in,
                              void* d_out, int out_size)
{
    const float* x      = (const float*)d_in[0];
    const float* wq     = (const float*)d_in[1];
    const float* wk     = (const float*)d_in[2];
    const float* wv     = (const float*)d_in[3];
    const float* w_proj = (const float*)d_in[4];
    const float* b_proj = (const float*)d_in[5];
    float* out = (float*)d_out;

    cudaFuncSetAttribute(gemm_f16<0>, cudaFuncAttributeMaxDynamicSharedMemorySize, 2 * QST);
    cudaFuncSetAttribute(gemm_f16<1>, cudaFuncAttributeMaxDynamicSharedMemorySize, 2 * QST);
    cudaFuncSetAttribute(attn_tc, cudaFuncAttributeMaxDynamicSharedMemorySize, ATT_SMEM);

    prep_all<<<(NX + NW1 + EMB * EMB + 255) / 256, 256>>>(x, wq, wk, wv, w_proj);

    gemm_f16<0><<<dim3(1152 / 128, BT / 128), 256, 2 * QST>>>(nullptr, nullptr);
    attn_tc<<<dim3(TT / 128, BB * HH), 256, ATT_SMEM>>>();
    gemm_f16<1><<<dim3(EMB / 128, BT / 128), 256, 2 * QST>>>(b_proj, out);
}

// round 12
// speedup vs baseline: 1.9115x; 1.1669x over previous
#include <cuda_runtime.h>
#include <cuda_bf16.h>
#include <cuda_fp16.h>
#include <cstdint>

#define BB 256
#define TT 256
#define EMB 384
#define HH 6
#define DD 64
#define BT (BB*TT)

// ---------------------------------------------------------------------------
// Scratch (__device__ globals — allocation-free rule).  Pure fp16 pipeline.
// ---------------------------------------------------------------------------
__device__ __align__(16) __half g_qhi[BB * HH * TT * DD];
__device__ __align__(16) __half g_khi[BB * HH * TT * DD];
__device__ __align__(16) __half g_vhi[BB * HH * TT * DD];
__device__ __align__(16) __half g_xhi[BT * EMB];
__device__ __align__(16) __half g_wthi[3 * HH * DD * EMB];  // [n=z*384+h*64+d][e]
__device__ __align__(16) __half g_wphi[EMB * EMB];          // [n][k]
__device__ __align__(16) __half g_atthi[BT * EMB];

// ---------------------------------------------------------------------------
// mma.sync / ldmatrix / cp.async helpers
// ---------------------------------------------------------------------------
__device__ __forceinline__ uint32_t smem_u32(const void* p) {
    uint32_t a;
    asm("{ .reg .u64 t; cvta.to.shared.u64 t, %1; cvt.u32.u64 %0, t; }"
        : "=r"(a) : "l"(p));
    return a;
}
__device__ __forceinline__ void ldm4(uint32_t* r, uint32_t addr) {
    asm volatile("ldmatrix.sync.aligned.m8n8.x4.shared.b16 {%0,%1,%2,%3}, [%4];"
        : "=r"(r[0]), "=r"(r[1]), "=r"(r[2]), "=r"(r[3]) : "r"(addr));
}
__device__ __forceinline__ void ldm4t(uint32_t* r, uint32_t addr) {
    asm volatile("ldmatrix.sync.aligned.m8n8.x4.trans.shared.b16 {%0,%1,%2,%3}, [%4];"
        : "=r"(r[0]), "=r"(r[1]), "=r"(r[2]), "=r"(r[3]) : "r"(addr));
}
__device__ __forceinline__ void mma_f16(float* c, const uint32_t* a, const uint32_t* b) {
    asm volatile(
        "mma.sync.aligned.m16n8k16.row.col.f32.f16.f16.f32 "
        "{%0,%1,%2,%3}, {%4,%5,%6,%7}, {%8,%9}, {%0,%1,%2,%3};"
        : "+f"(c[0]), "+f"(c[1]), "+f"(c[2]), "+f"(c[3])
        : "r"(a[0]), "r"(a[1]), "r"(a[2]), "r"(a[3]), "r"(b[0]), "r"(b[1]));
}
__device__ __forceinline__ void cp16(uint32_t dst, const void* src) {
    asm volatile("cp.async.cg.shared.global [%0], [%1], 16;" :: "r"(dst), "l"(src));
}
#define CP_COMMIT() asm volatile("cp.async.commit_group;" ::: "memory")
#define CP_WAIT_1() asm volatile("cp.async.wait_group 1;" ::: "memory")
#define CP_WAIT_ALL() asm volatile("cp.async.wait_group 0;" ::: "memory")

__device__ __forceinline__ uint32_t pack_h2(float lo, float hi) {
    __half2 h = __floats2half2_rn(lo, hi);
    return *(uint32_t*)&h;
}

// 64B-row tile swizzle (4 units of 16B): u ^ ((r>>1)&3)
__device__ __forceinline__ uint32_t swz(uint32_t r, uint32_t u) {
    return (r << 6) + ((u ^ ((r >> 1) & 3u)) << 4);
}
// 128B-row tile swizzle (8 units of 16B): u ^ (r&7)
__device__ __forceinline__ uint32_t swz8(uint32_t r, uint32_t u) {
    return (r << 7) + ((u ^ (r & 7u)) << 4);
}

// ---------------------------------------------------------------------------
// Single prep kernel: x -> fp16; weights transposed -> fp16
// ---------------------------------------------------------------------------
#define NX  (BT * EMB)
#define NW1 (3 * HH * DD * EMB)
__global__ void prep_all(const float* __restrict__ x,
                         const float* __restrict__ wq, const float* __restrict__ wk,
                         const float* __restrict__ wv, const float* __restrict__ wp)
{
    int i = blockIdx.x * 256 + threadIdx.x;
    if (i < NX) {
        g_xhi[i] = __float2half(x[i]);
    } else if (i < NX + NW1) {
        int j = i - NX;
        int e = j % EMB;
        int d = (j / EMB) % DD;
        int h = (j / (EMB * DD)) % HH;
        int z = j / (EMB * DD * HH);
        const float* w = (z == 0) ? wq : (z == 1) ? wk : wv;
        g_wthi[j] = __float2half(w[(h * EMB + e) * DD + d]);
    } else if (i < NX + NW1 + EMB * EMB) {
        int j = i - NX - NW1;
        int k = j % EMB;
        int n = j / EMB;
        g_wphi[j] = __float2half(wp[k * EMB + n]);
    }
}

// ---------------------------------------------------------------------------
// QKV GEMM: pure 1-term fp16, 3-stage cp.async pipeline.
// Stage = Ahi(8KB)+Bhi(8KB) = 16KB; 3 stages = 48KB; 2 CTAs/SM.
// ---------------------------------------------------------------------------
#define QST 16384
#define QOFF_AH 0
#define QOFF_BH 8192

__global__ __launch_bounds__(256, 2) void gemm_qkv()
{
    extern __shared__ char sm[];
    const uint32_t sb = smem_u32(sm);

    const char* AhiB = (const char*)g_xhi;
    const char* BhiB = (const char*)g_wthi;

    const int tid  = threadIdx.x;
    const int wid  = tid >> 5;
    const int lane = tid & 31;
    const int m0   = blockIdx.y * 128;
    const int n0   = blockIdx.x * 128;

    const int lr = tid >> 2;
    const int lu = tid & 3;

    const int wm   = (wid >> 1) * 32;
    const int wn   = (wid & 1) * 64;
    const int a_r  = wm + (lane & 15);
    const int a_u0 = (lane >> 4);
    const int b_r  = wn + ((lane >> 4) & 1) * 8 + (lane & 7);
    const int b_u0 = (lane >> 3) & 1;

    // issue chunk kc into stage kc%3 (two cp.async rows per thread per array)
    auto issue = [&](int kc) {
        const uint32_t s0 = sb + (kc % 3) * QST;
        const int ko = kc * 64;
        #pragma unroll
        for (int j = 0; j < 2; j++) {
            int r = lr + j * 64;
            cp16(s0 + QOFF_AH + swz(r, lu), AhiB + (size_t)(m0 + r) * 768 + ko + lu * 16);
            cp16(s0 + QOFF_BH + swz(r, lu), BhiB + (size_t)(n0 + r) * 768 + ko + lu * 16);
        }
        CP_COMMIT();
    };

    issue(0);
    issue(1);

    float c[2][8][4];
    #pragma unroll
    for (int mt = 0; mt < 2; mt++)
        #pragma unroll
        for (int nt = 0; nt < 8; nt++)
            #pragma unroll
            for (int q = 0; q < 4; q++) c[mt][nt][q] = 0.0f;

    for (int kc = 0; kc < 12; kc++) {
        CP_WAIT_1();             // group kc complete (≤1 outstanding)
        __syncthreads();         // all threads' stage-kc data visible
        if (kc + 2 < 12) issue(kc + 2);

        const uint32_t base = sb + (kc % 3) * QST;
        #pragma unroll
        for (int ks = 0; ks < 2; ks++) {
            uint32_t ahi[2][4], bhi[8][2];
            #pragma unroll
            for (int mt = 0; mt < 2; mt++) {
                uint32_t r = a_r + mt * 16;
                uint32_t u = ks * 2 + a_u0;
                ldm4(ahi[mt], base + QOFF_AH + swz(r, u));
            }
            #pragma unroll
            for (int p = 0; p < 4; p++) {
                uint32_t r = b_r + p * 16;
                uint32_t u = ks * 2 + b_u0;
                uint32_t t4[4];
                ldm4(t4, base + QOFF_BH + swz(r, u));
                bhi[2 * p][0] = t4[0]; bhi[2 * p][1] = t4[1];
                bhi[2 * p + 1][0] = t4[2]; bhi[2 * p + 1][1] = t4[3];
            }
            #pragma unroll
            for (int mt = 0; mt < 2; mt++)
                #pragma unroll
                for (int nt = 0; nt < 8; nt++)
                    mma_f16(c[mt][nt], ahi[mt], bhi[nt]);
        }
    }

    const int row0 = lane >> 2;
    const int col0 = (lane & 3) * 2;
    const int z = n0 / 384;
    const int nloc = n0 % 384;
    const float scl = (z == 0) ? 0.125f : 1.0f;
    __half* dhi = (z == 0) ? g_qhi : (z == 1) ? g_khi : g_vhi;
    #pragma unroll
    for (int mt = 0; mt < 2; mt++)
        #pragma unroll
        for (int half = 0; half < 2; half++) {
            int m = m0 + wm + mt * 16 + row0 + half * 8;
            int b = m >> 8, t = m & 255;
            #pragma unroll
            for (int nt = 0; nt < 8; nt++) {
                int n = nloc + wn + nt * 8 + col0;
                int h = n >> 6, d = n & 63;
                size_t idx = (((size_t)b * HH + h) * TT + t) * DD + d;
                *(uint32_t*)(dhi + idx) =
                    pack_h2(c[mt][nt][half * 2] * scl, c[mt][nt][half * 2 + 1] * scl);
            }
        }
}

// ---------------------------------------------------------------------------
// Output projection: 1-term fp16, R11-proven register-prefetch skeleton.
// ---------------------------------------------------------------------------
__global__ __launch_bounds__(256, 2) void gemm_proj(const float* __restrict__ bias,
                                                    float* __restrict__ outp)
{
    extern __shared__ char sm[];
    const uint32_t sb = smem_u32(sm);

    const char* AhiB = (const char*)g_atthi;
    const char* BhiB = (const char*)g_wphi;

    const int tid  = threadIdx.x;
    const int wid  = tid >> 5;
    const int lane = tid & 31;
    const int m0   = blockIdx.y * 128;
    const int n0   = blockIdx.x * 128;

    const int lr = tid >> 2;
    const int lu = tid & 3;

    const int wm   = (wid >> 1) * 32;
    const int wn   = (wid & 1) * 64;
    const int a_r  = wm + (lane & 15);
    const int a_u0 = (lane >> 4);
    const int b_r  = wn + ((lane >> 4) & 1) * 8 + (lane & 7);
    const int b_u0 = (lane >> 3) & 1;

    float c[2][8][4];
    #pragma unroll
    for (int mt = 0; mt < 2; mt++)
        #pragma unroll
        for (int nt = 0; nt < 8; nt++)
            #pragma unroll
            for (int q = 0; q < 4; q++) c[mt][nt][q] = 0.0f;

    {
        #pragma unroll
        for (int j = 0; j < 2; j++) {
            int r = lr + j * 64;
            *(uint4*)(sm + QOFF_AH + swz(r, lu)) =
                *(const uint4*)(AhiB + (size_t)(m0 + r) * 768 + lu * 16);
            *(uint4*)(sm + QOFF_BH + swz(r, lu)) =
                *(const uint4*)(BhiB + (size_t)(n0 + r) * 768 + lu * 16);
        }
    }
    __syncthreads();

    int stage = 0;
    for (int kc = 0; kc < 12; kc++) {
        uint4 v[4];
        if (kc < 11) {
            const int ko = (kc + 1) * 64;
            #pragma unroll
            for (int j = 0; j < 2; j++) {
                int r = lr + j * 64;
                v[j * 2 + 0] = *(const uint4*)(AhiB + (size_t)(m0 + r) * 768 + ko + lu * 16);
                v[j * 2 + 1] = *(const uint4*)(BhiB + (size_t)(n0 + r) * 768 + ko + lu * 16);
            }
        }

        const uint32_t base = sb + stage * QST;
        #pragma unroll
        for (int ks = 0; ks < 2; ks++) {
            uint32_t ahi[2][4], bhi[8][2];
            #pragma unroll
            for (int mt = 0; mt < 2; mt++) {
                uint32_t r = a_r + mt * 16;
                uint32_t u = ks * 2 + a_u0;
                ldm4(ahi[mt], base + QOFF_AH + swz(r, u));
            }
            #pragma unroll
            for (int p = 0; p < 4; p++) {
                uint32_t r = b_r + p * 16;
                uint32_t u = ks * 2 + b_u0;
                uint32_t t4[4];
                ldm4(t4, base + QOFF_BH + swz(r, u));
                bhi[2 * p][0] = t4[0]; bhi[2 * p][1] = t4[1];
                bhi[2 * p + 1][0] = t4[2]; bhi[2 * p + 1][1] = t4[3];
            }
            #pragma unroll
            for (int mt = 0; mt < 2; mt++)
                #pragma unroll
                for (int nt = 0; nt < 8; nt++)
                    mma_f16(c[mt][nt], ahi[mt], bhi[nt]);
        }

        if (kc < 11) {
            char* dst = sm + (stage ^ 1) * QST;
            #pragma unroll
            for (int j = 0; j < 2; j++) {
                int r = lr + j * 64;
                *(uint4*)(dst + QOFF_AH + swz(r, lu)) = v[j * 2 + 0];
                *(uint4*)(dst + QOFF_BH + swz(r, lu)) = v[j * 2 + 1];
            }
        }
        __syncthreads();
        stage ^= 1;
    }

    const int row0 = lane >> 2;
    const int col0 = (lane & 3) * 2;
    #pragma unroll
    for (int mt = 0; mt < 2; mt++)
        #pragma unroll
        for (int half = 0; half < 2; half++) {
            int m = m0 + wm + mt * 16 + row0 + half * 8;
            #pragma unroll
            for (int nt = 0; nt < 8; nt++) {
                int n = n0 + wn + nt * 8 + col0;
                float2 val = make_float2(c[mt][nt][half * 2] + bias[n],
                                         c[mt][nt][half * 2 + 1] + bias[n + 1]);
                *(float2*)(outp + (size_t)m * EMB + n) = val;
            }
        }
}

// ---------------------------------------------------------------------------
// fp16 flash attention: S 1-term, PV 1-term.
// smem: Q 16KB + 2 stages x (K 16KB + V 16KB) = 80KB.
// ---------------------------------------------------------------------------
#define AQHI 0
#define AKV0 16384
#define ATT_SMEM 81920

__global__ __launch_bounds__(256) void attn_tc()
{
    extern __shared__ char sm[];
    const uint32_t sb = smem_u32(sm);
    const int qt  = blockIdx.x;
    const int bh  = blockIdx.y;
    const int tid = threadIdx.x;
    const int wid = tid >> 5;
    const int lane = tid & 31;

    const __half* qhi = g_qhi + ((size_t)bh * TT + qt * 128) * DD;
    const __half* khi = g_khi + (size_t)bh * TT * DD;
    const __half* vhi = g_vhi + (size_t)bh * TT * DD;

    #pragma unroll
    for (int j = 0; j < 4; j++) {
        int idx = tid + 256 * j;
        int r = idx >> 3;
        int u = idx & 7;
        cp16(sb + AQHI + swz8(r, u), qhi + (size_t)r * DD + u * 8);
    }
    #pragma unroll
    for (int j = 0; j < 8; j++) {
        int idx = tid + 256 * j;
        int arr = idx >> 10;
        int r = (idx >> 3) & 127;
        int u = idx & 7;
        const __half* src = arr ? vhi : khi;
        cp16(sb + AKV0 + arr * 16384 + swz8(r, u), src + (size_t)r * DD + u * 8);
    }
    CP_COMMIT();
    CP_WAIT_ALL();
    __syncthreads();

    uint32_t qfh[4][4];
    {
        int ar = wid * 16 + (lane & 15);
        #pragma unroll
        for (int kc = 0; kc < 4; kc++) {
            int u = kc * 2 + (lane >> 4);
            ldm4(qfh[kc], sb + AQHI + swz8(ar, u));
        }
    }

    float o[8][4];
    #pragma unroll
    for (int nt = 0; nt < 8; nt++)
        #pragma unroll
        for (int q = 0; q < 4; q++) o[nt][q] = 0.0f;
    float mx[2] = {-1e30f, -1e30f};
    float lsum[2] = {0.0f, 0.0f};

    for (int kt = 0; kt <= qt; kt++) {
        const uint32_t kvb = sb + AKV0 + (kt & 1) * 32768;

        if (kt < qt) {
            #pragma unroll
            for (int j = 0; j < 8; j++) {
                int idx = tid + 256 * j;
                int arr = idx >> 10;
                int r = (idx >> 3) & 127;
                int u = idx & 7;
                const __half* src = arr ? vhi : khi;
                cp16(sb + AKV0 + ((kt + 1) & 1) * 32768 + arr * 16384 + swz8(r, u),
                     src + ((size_t)(kt + 1) * 128 + r) * DD + u * 8);
            }
            CP_COMMIT();
        }

        float s[16][4];
        #pragma unroll
        for (int nt = 0; nt < 16; nt++)
            #pragma unroll
            for (int q = 0; q < 4; q++) s[nt][q] = 0.0f;

        #pragma unroll
        for (int np = 0; np < 8; np++) {
            int br = np * 16 + ((lane >> 4) & 1) * 8 + (lane & 7);
            #pragma unroll
            for (int kc = 0; kc < 4; kc++) {
                int u = kc * 2 + ((lane >> 3) & 1);
                uint32_t th[4];
                ldm4(th, kvb + swz8(br, u));
                uint32_t b0h[2] = {th[0], th[1]}, b1h[2] = {th[2], th[3]};
                mma_f16(s[2 * np], qfh[kc], b0h);
                mma_f16(s[2 * np + 1], qfh[kc], b1h);
            }
        }

        if (kt == qt) {
            #pragma unroll
            for (int nt = 0; nt < 16; nt++)
                #pragma unroll
                for (int q = 0; q < 4; q++) {
                    int col = nt * 8 + (lane & 3) * 2 + (q & 1);
                    int row = wid * 16 + (lane >> 2) + (q >> 1) * 8;
                    if (col > row) s[nt][q] = -1e30f;
                }
        }

        float al[2];
        #pragma unroll
        for (int hf = 0; hf < 2; hf++) {
            float rm = -1e30f;
            #pragma unroll
            for (int nt = 0; nt < 16; nt++)
                rm = fmaxf(rm, fmaxf(s[nt][hf * 2], s[nt][hf * 2 + 1]));
            rm = fmaxf(rm, __shfl_xor_sync(0xffffffffu, rm, 1));
            rm = fmaxf(rm, __shfl_xor_sync(0xffffffffu, rm, 2));
            float mn = fmaxf(mx[hf], rm);
            al[hf] = __expf(mx[hf] - mn);
            mx[hf] = mn;
            float ps = 0.0f;
            #pragma unroll
            for (int nt = 0; nt < 16; nt++) {
                s[nt][hf * 2]     = __expf(s[nt][hf * 2] - mn);
                s[nt][hf * 2 + 1] = __expf(s[nt][hf * 2 + 1] - mn);
                ps += s[nt][hf * 2] + s[nt][hf * 2 + 1];
            }
            ps += __shfl_xor_sync(0xffffffffu, ps, 1);
            ps += __shfl_xor_sync(0xffffffffu, ps, 2);
            lsum[hf] = lsum[hf] * al[hf] + ps;
        }
        #pragma unroll
        for (int nt = 0; nt < 8; nt++) {
            o[nt][0] *= al[0]; o[nt][1] *= al[0];
            o[nt][2] *= al[1]; o[nt][3] *= al[1];
        }

        // O += P V (1-term)
        #pragma unroll
        for (int kc = 0; kc < 8; kc++) {
            uint32_t ah[4];
            ah[0] = pack_h2(s[2 * kc][0], s[2 * kc][1]);
            ah[1] = pack_h2(s[2 * kc][2], s[2 * kc][3]);
            ah[2] = pack_h2(s[2 * kc + 1][0], s[2 * kc + 1][1]);
            ah[3] = pack_h2(s[2 * kc + 1][2], s[2 * kc + 1][3]);

            int vr = kc * 16 + ((lane >> 3) & 1) * 8 + (lane & 7);
            #pragma unroll
            for (int ntp = 0; ntp < 4; ntp++) {
                int u = ntp * 2 + (lane >> 4);
                uint32_t th[4];
                ldm4t(th, kvb + 16384 + swz8(vr, u));
                uint32_t b0h[2] = {th[0], th[1]}, b1h[2] = {th[2], th[3]};
                mma_f16(o[2 * ntp], ah, b0h);
                mma_f16(o[2 * ntp + 1], ah, b1h);
            }
        }

        if (kt < qt) {
            CP_WAIT_ALL();
            __syncthreads();
        }
    }

    const int b = bh / HH, h = bh % HH;
    #pragma unroll
    for (int hf = 0; hf < 2; hf++) {
        float inv = 1.0f / lsum[hf];
        int t = qt * 128 + wid * 16 + (lane >> 2) + hf * 8;
        size_t rowb = ((size_t)b * TT + t) * EMB + h * 64 + (lane & 3) * 2;
        #pragma unroll
        for (int nt = 0; nt < 8; nt++)
            *(uint32_t*)(g_atthi + rowb + nt * 8) =
                pack_h2(o[nt][hf * 2] * inv, o[nt][hf * 2 + 1] * inv);
    }
}

// ---------------------------------------------------------------------------
extern "C" void kernel_launch(void* const* d_in, const int* in_sizes, int n_in,
                              void* d_out, int out_size)
{
    const float* x      = (const float*)d_in[0];
    const float* wq     = (const float*)d_in[1];
    const float* wk     = (const float*)d_in[2];
    const float* wv     = (const float*)d_in[3];
    const float* w_proj = (const float*)d_in[4];
    const float* b_proj = (const float*)d_in[5];
    float* out = (float*)d_out;

    cudaFuncSetAttribute(gemm_qkv, cudaFuncAttributeMaxDynamicSharedMemorySize, 3 * QST);
    cudaFuncSetAttribute(gemm_proj, cudaFuncAttributeMaxDynamicSharedMemorySize, 2 * QST);
    cudaFuncSetAttribute(attn_tc, cudaFuncAttributeMaxDynamicSharedMemorySize, ATT_SMEM);

    prep_all<<<(NX + NW1 + EMB * EMB + 255) / 256, 256>>>(x, wq, wk, wv, w_proj);

    gemm_qkv<<<dim3(1152 / 128, BT / 128), 256, 3 * QST>>>();
    attn_tc<<<dim3(TT / 128, BB * HH), 256, ATT_SMEM>>>();
    gemm_proj<<<dim3(EMB / 128, BT / 128), 256, 2 * QST>>>(b_proj, out);
}

// round 13
// speedup vs baseline: 2.1932x; 1.1474x over previous
#include <cuda_runtime.h>
#include <cuda_bf16.h>
#include <cuda_fp16.h>
#include <cstdint>

#define BB 256
#define TT 256
#define EMB 384
#define HH 6
#define DD 64
#define BT (BB*TT)

// ---------------------------------------------------------------------------
// Scratch (__device__ globals — allocation-free rule).  Pure fp16 pipeline.
// ---------------------------------------------------------------------------
__device__ __align__(16) __half g_qhi[BB * HH * TT * DD];
__device__ __align__(16) __half g_khi[BB * HH * TT * DD];
__device__ __align__(16) __half g_vhi[BB * HH * TT * DD];
__device__ __align__(16) __half g_xhi[BT * EMB];
__device__ __align__(16) __half g_wthi[3 * HH * DD * EMB];  // [n=z*384+h*64+d][e]
__device__ __align__(16) __half g_wphi[EMB * EMB];          // [n][k]
__device__ __align__(16) __half g_atthi[BT * EMB];

// ---------------------------------------------------------------------------
// mma.sync / ldmatrix / cp.async helpers
// ---------------------------------------------------------------------------
__device__ __forceinline__ uint32_t smem_u32(const void* p) {
    uint32_t a;
    asm("{ .reg .u64 t; cvta.to.shared.u64 t, %1; cvt.u32.u64 %0, t; }"
        : "=r"(a) : "l"(p));
    return a;
}
__device__ __forceinline__ void ldm4(uint32_t* r, uint32_t addr) {
    asm volatile("ldmatrix.sync.aligned.m8n8.x4.shared.b16 {%0,%1,%2,%3}, [%4];"
        : "=r"(r[0]), "=r"(r[1]), "=r"(r[2]), "=r"(r[3]) : "r"(addr));
}
__device__ __forceinline__ void ldm4t(uint32_t* r, uint32_t addr) {
    asm volatile("ldmatrix.sync.aligned.m8n8.x4.trans.shared.b16 {%0,%1,%2,%3}, [%4];"
        : "=r"(r[0]), "=r"(r[1]), "=r"(r[2]), "=r"(r[3]) : "r"(addr));
}
__device__ __forceinline__ void mma_f16(float* c, const uint32_t* a, const uint32_t* b) {
    asm volatile(
        "mma.sync.aligned.m16n8k16.row.col.f32.f16.f16.f32 "
        "{%0,%1,%2,%3}, {%4,%5,%6,%7}, {%8,%9}, {%0,%1,%2,%3};"
        : "+f"(c[0]), "+f"(c[1]), "+f"(c[2]), "+f"(c[3])
        : "r"(a[0]), "r"(a[1]), "r"(a[2]), "r"(a[3]), "r"(b[0]), "r"(b[1]));
}
__device__ __forceinline__ void cp16(uint32_t dst, const void* src) {
    asm volatile("cp.async.cg.shared.global [%0], [%1], 16;" :: "r"(dst), "l"(src));
}
#define CP_COMMIT() asm volatile("cp.async.commit_group;" ::: "memory")
#define CP_WAIT_1() asm volatile("cp.async.wait_group 1;" ::: "memory")
#define CP_WAIT_ALL() asm volatile("cp.async.wait_group 0;" ::: "memory")

__device__ __forceinline__ uint32_t pack_h2(float lo, float hi) {
    __half2 h = __floats2half2_rn(lo, hi);
    return *(uint32_t*)&h;
}

// 64B-row tile swizzle (4 units of 16B): u ^ ((r>>1)&3)
__device__ __forceinline__ uint32_t swz(uint32_t r, uint32_t u) {
    return (r << 6) + ((u ^ ((r >> 1) & 3u)) << 4);
}
// 128B-row tile swizzle (8 units of 16B): u ^ (r&7)
__device__ __forceinline__ uint32_t swz8(uint32_t r, uint32_t u) {
    return (r << 7) + ((u ^ (r & 7u)) << 4);
}

// ---------------------------------------------------------------------------
// Prep: x -> fp16 (vectorized float4 -> half2 x2); weights transposed -> fp16
// ---------------------------------------------------------------------------
#define NX   (BT * EMB)
#define NX4  (NX / 4)
#define NW1  (3 * HH * DD * EMB)
__global__ void prep_all(const float* __restrict__ x,
                         const float* __restrict__ wq, const float* __restrict__ wk,
                         const float* __restrict__ wv, const float* __restrict__ wp)
{
    int i = blockIdx.x * 256 + threadIdx.x;
    if (i < NX4) {
        float4 f = *(const float4*)(x + (size_t)i * 4);
        uint32_t p0 = pack_h2(f.x, f.y);
        uint32_t p1 = pack_h2(f.z, f.w);
        *(uint2*)(g_xhi + (size_t)i * 4) = make_uint2(p0, p1);
    } else if (i < NX4 + NW1) {
        int j = i - NX4;
        int e = j % EMB;
        int d = (j / EMB) % DD;
        int h = (j / (EMB * DD)) % HH;
        int z = j / (EMB * DD * HH);
        const float* w = (z == 0) ? wq : (z == 1) ? wk : wv;
        g_wthi[j] = __float2half(w[(h * EMB + e) * DD + d]);
    } else if (i < NX4 + NW1 + EMB * EMB) {
        int j = i - NX4 - NW1;
        int k = j % EMB;
        int n = j / EMB;
        g_wphi[j] = __float2half(wp[k * EMB + n]);
    }
}

// ---------------------------------------------------------------------------
// Unified 1-term fp16 GEMM, 3-stage cp.async pipeline (R12-proven skeleton).
// C[M,N] = A[M,384] x B[384,N].
// MODE 0: qkv (B = g_wthi, N=1152; writes q/k/v fp16, q pre-scaled 1/8)
// MODE 1: proj (B = g_wphi, N=384; adds bias, writes fp32 out)
// Stage = Ahi(8KB)+Bhi(8KB) = 16KB; 3 stages = 48KB; 2 CTAs/SM.
// ---------------------------------------------------------------------------
#define QST 16384
#define QOFF_AH 0
#define QOFF_BH 8192

template<int MODE>
__global__ __launch_bounds__(256, 2) void gemm_f16(const float* __restrict__ bias,
                                                   float* __restrict__ outp)
{
    extern __shared__ char sm[];
    const uint32_t sb = smem_u32(sm);

    const char* AhiB = (const char*)(MODE == 0 ? g_xhi : g_atthi);
    const char* BhiB = (const char*)(MODE == 0 ? g_wthi : g_wphi);

    const int tid  = threadIdx.x;
    const int wid  = tid >> 5;
    const int lane = tid & 31;
    const int m0   = blockIdx.y * 128;
    const int n0   = blockIdx.x * 128;

    const int lr = tid >> 2;
    const int lu = tid & 3;

    const int wm   = (wid >> 1) * 32;
    const int wn   = (wid & 1) * 64;
    const int a_r  = wm + (lane & 15);
    const int a_u0 = (lane >> 4);
    const int b_r  = wn + ((lane >> 4) & 1) * 8 + (lane & 7);
    const int b_u0 = (lane >> 3) & 1;

    auto issue = [&](int kc) {
        const uint32_t s0 = sb + (kc % 3) * QST;
        const int ko = kc * 64;
        #pragma unroll
        for (int j = 0; j < 2; j++) {
            int r = lr + j * 64;
            cp16(s0 + QOFF_AH + swz(r, lu), AhiB + (size_t)(m0 + r) * 768 + ko + lu * 16);
            cp16(s0 + QOFF_BH + swz(r, lu), BhiB + (size_t)(n0 + r) * 768 + ko + lu * 16);
        }
        CP_COMMIT();
    };

    issue(0);
    issue(1);

    float c[2][8][4];
    #pragma unroll
    for (int mt = 0; mt < 2; mt++)
        #pragma unroll
        for (int nt = 0; nt < 8; nt++)
            #pragma unroll
            for (int q = 0; q < 4; q++) c[mt][nt][q] = 0.0f;

    for (int kc = 0; kc < 12; kc++) {
        CP_WAIT_1();
        __syncthreads();
        if (kc + 2 < 12) issue(kc + 2);

        const uint32_t base = sb + (kc % 3) * QST;
        #pragma unroll
        for (int ks = 0; ks < 2; ks++) {
            uint32_t ahi[2][4], bhi[8][2];
            #pragma unroll
            for (int mt = 0; mt < 2; mt++) {
                uint32_t r = a_r + mt * 16;
                uint32_t u = ks * 2 + a_u0;
                ldm4(ahi[mt], base + QOFF_AH + swz(r, u));
            }
            #pragma unroll
            for (int p = 0; p < 4; p++) {
                uint32_t r = b_r + p * 16;
                uint32_t u = ks * 2 + b_u0;
                uint32_t t4[4];
                ldm4(t4, base + QOFF_BH + swz(r, u));
                bhi[2 * p][0] = t4[0]; bhi[2 * p][1] = t4[1];
                bhi[2 * p + 1][0] = t4[2]; bhi[2 * p + 1][1] = t4[3];
            }
            #pragma unroll
            for (int mt = 0; mt < 2; mt++)
                #pragma unroll
                for (int nt = 0; nt < 8; nt++)
                    mma_f16(c[mt][nt], ahi[mt], bhi[nt]);
        }
    }

    const int row0 = lane >> 2;
    const int col0 = (lane & 3) * 2;

    if (MODE == 0) {
        const int z = n0 / 384;
        const int nloc = n0 % 384;
        const float scl = (z == 0) ? 0.125f : 1.0f;
        __half* dhi = (z == 0) ? g_qhi : (z == 1) ? g_khi : g_vhi;
        #pragma unroll
        for (int mt = 0; mt < 2; mt++)
            #pragma unroll
            for (int half = 0; half < 2; half++) {
                int m = m0 + wm + mt * 16 + row0 + half * 8;
                int b = m >> 8, t = m & 255;
                #pragma unroll
                for (int nt = 0; nt < 8; nt++) {
                    int n = nloc + wn + nt * 8 + col0;
                    int h = n >> 6, d = n & 63;
                    size_t idx = (((size_t)b * HH + h) * TT + t) * DD + d;
                    *(uint32_t*)(dhi + idx) =
                        pack_h2(c[mt][nt][half * 2] * scl, c[mt][nt][half * 2 + 1] * scl);
                }
            }
    } else {
        #pragma unroll
        for (int mt = 0; mt < 2; mt++)
            #pragma unroll
            for (int half = 0; half < 2; half++) {
                int m = m0 + wm + mt * 16 + row0 + half * 8;
                #pragma unroll
                for (int nt = 0; nt < 8; nt++) {
                    int n = n0 + wn + nt * 8 + col0;
                    float2 val = make_float2(c[mt][nt][half * 2] + bias[n],
                                             c[mt][nt][half * 2 + 1] + bias[n + 1]);
                    *(float2*)(outp + (size_t)m * EMB + n) = val;
                }
            }
    }
}

// ---------------------------------------------------------------------------
// fp16 flash attention: S 1-term, PV 1-term — exact R12-proven version.
// smem: Q 16KB + 2 stages x (K 16KB + V 16KB) = 80KB.
// ---------------------------------------------------------------------------
#define AQHI 0
#define AKV0 16384
#define ATT_SMEM 81920

__global__ __launch_bounds__(256) void attn_tc()
{
    extern __shared__ char sm[];
    const uint32_t sb = smem_u32(sm);
    const int qt  = blockIdx.x;
    const int bh  = blockIdx.y;
    const int tid = threadIdx.x;
    const int wid = tid >> 5;
    const int lane = tid & 31;

    const __half* qhi = g_qhi + ((size_t)bh * TT + qt * 128) * DD;
    const __half* khi = g_khi + (size_t)bh * TT * DD;
    const __half* vhi = g_vhi + (size_t)bh * TT * DD;

    #pragma unroll
    for (int j = 0; j < 4; j++) {
        int idx = tid + 256 * j;
        int r = idx >> 3;
        int u = idx & 7;
        cp16(sb + AQHI + swz8(r, u), qhi + (size_t)r * DD + u * 8);
    }
    #pragma unroll
    for (int j = 0; j < 8; j++) {
        int idx = tid + 256 * j;
        int arr = idx >> 10;
        int r = (idx >> 3) & 127;
        int u = idx & 7;
        const __half* src = arr ? vhi : khi;
        cp16(sb + AKV0 + arr * 16384 + swz8(r, u), src + (size_t)r * DD + u * 8);
    }
    CP_COMMIT();
    CP_WAIT_ALL();
    __syncthreads();

    uint32_t qfh[4][4];
    {
        int ar = wid * 16 + (lane & 15);
        #pragma unroll
        for (int kc = 0; kc < 4; kc++) {
            int u = kc * 2 + (lane >> 4);
            ldm4(qfh[kc], sb + AQHI + swz8(ar, u));
        }
    }

    float o[8][4];
    #pragma unroll
    for (int nt = 0; nt < 8; nt++)
        #pragma unroll
        for (int q = 0; q < 4; q++) o[nt][q] = 0.0f;
    float mx[2] = {-1e30f, -1e30f};
    float lsum[2] = {0.0f, 0.0f};

    for (int kt = 0; kt <= qt; kt++) {
        const uint32_t kvb = sb + AKV0 + (kt & 1) * 32768;

        if (kt < qt) {
            #pragma unroll
            for (int j = 0; j < 8; j++) {
                int idx = tid + 256 * j;
                int arr = idx >> 10;
                int r = (idx >> 3) & 127;
                int u = idx & 7;
                const __half* src = arr ? vhi : khi;
                cp16(sb + AKV0 + ((kt + 1) & 1) * 32768 + arr * 16384 + swz8(r, u),
                     src + ((size_t)(kt + 1) * 128 + r) * DD + u * 8);
            }
            CP_COMMIT();
        }

        float s[16][4];
        #pragma unroll
        for (int nt = 0; nt < 16; nt++)
            #pragma unroll
            for (int q = 0; q < 4; q++) s[nt][q] = 0.0f;

        #pragma unroll
        for (int np = 0; np < 8; np++) {
            int br = np * 16 + ((lane >> 4) & 1) * 8 + (lane & 7);
            #pragma unroll
            for (int kc = 0; kc < 4; kc++) {
                int u = kc * 2 + ((lane >> 3) & 1);
                uint32_t th[4];
                ldm4(th, kvb + swz8(br, u));
                uint32_t b0h[2] = {th[0], th[1]}, b1h[2] = {th[2], th[3]};
                mma_f16(s[2 * np], qfh[kc], b0h);
                mma_f16(s[2 * np + 1], qfh[kc], b1h);
            }
        }

        if (kt == qt) {
            #pragma unroll
            for (int nt = 0; nt < 16; nt++)
                #pragma unroll
                for (int q = 0; q < 4; q++) {
                    int col = nt * 8 + (lane & 3) * 2 + (q & 1);
                    int row = wid * 16 + (lane >> 2) + (q >> 1) * 8;
                    if (col > row) s[nt][q] = -1e30f;
                }
        }

        float al[2];
        #pragma unroll
        for (int hf = 0; hf < 2; hf++) {
            float rm = -1e30f;
            #pragma unroll
            for (int nt = 0; nt < 16; nt++)
                rm = fmaxf(rm, fmaxf(s[nt][hf * 2], s[nt][hf * 2 + 1]));
            rm = fmaxf(rm, __shfl_xor_sync(0xffffffffu, rm, 1));
            rm = fmaxf(rm, __shfl_xor_sync(0xffffffffu, rm, 2));
            float mn = fmaxf(mx[hf], rm);
            al[hf] = __expf(mx[hf] - mn);
            mx[hf] = mn;
            float ps = 0.0f;
            #pragma unroll
            for (int nt = 0; nt < 16; nt++) {
                s[nt][hf * 2]     = __expf(s[nt][hf * 2] - mn);
                s[nt][hf * 2 + 1] = __expf(s[nt][hf * 2 + 1] - mn);
                ps += s[nt][hf * 2] + s[nt][hf * 2 + 1];
            }
            ps += __shfl_xor_sync(0xffffffffu, ps, 1);
            ps += __shfl_xor_sync(0xffffffffu, ps, 2);
            lsum[hf] = lsum[hf] * al[hf] + ps;
        }
        #pragma unroll
        for (int nt = 0; nt < 8; nt++) {
            o[nt][0] *= al[0]; o[nt][1] *= al[0];
            o[nt][2] *= al[1]; o[nt][3] *= al[1];
        }

        #pragma unroll
        for (int kc = 0; kc < 8; kc++) {
            uint32_t ah[4];
            ah[0] = pack_h2(s[2 * kc][0], s[2 * kc][1]);
            ah[1] = pack_h2(s[2 * kc][2], s[2 * kc][3]);
            ah[2] = pack_h2(s[2 * kc + 1][0], s[2 * kc + 1][1]);
            ah[3] = pack_h2(s[2 * kc + 1][2], s[2 * kc + 1][3]);

            int vr = kc * 16 + ((lane >> 3) & 1) * 8 + (lane & 7);
            #pragma unroll
            for (int ntp = 0; ntp < 4; ntp++) {
                int u = ntp * 2 + (lane >> 4);
                uint32_t th[4];
                ldm4t(th, kvb + 16384 + swz8(vr, u));
                uint32_t b0h[2] = {th[0], th[1]}, b1h[2] = {th[2], th[3]};
                mma_f16(o[2 * ntp], ah, b0h);
                mma_f16(o[2 * ntp + 1], ah, b1h);
            }
        }

        if (kt < qt) {
            CP_WAIT_ALL();
            __syncthreads();
        }
    }

    const int b = bh / HH, h = bh % HH;
    #pragma unroll
    for (int hf = 0; hf < 2; hf++) {
        float inv = 1.0f / lsum[hf];
        int t = qt * 128 + wid * 16 + (lane >> 2) + hf * 8;
        size_t rowb = ((size_t)b * TT + t) * EMB + h * 64 + (lane & 3) * 2;
        #pragma unroll
        for (int nt = 0; nt < 8; nt++)
            *(uint32_t*)(g_atthi + rowb + nt * 8) =
                pack_h2(o[nt][hf * 2] * inv, o[nt][hf * 2 + 1] * inv);
    }
}

// ---------------------------------------------------------------------------
extern "C" void kernel_launch(void* const* d_in, const int* in_sizes, int n_in,
                              void* d_out, int out_size)
{
    const float* x      = (const float*)d_in[0];
    const float* wq     = (const float*)d_in[1];
    const float* wk     = (const float*)d_in[2];
    const float* wv     = (const float*)d_in[3];
    const float* w_proj = (const float*)d_in[4];
    const float* b_proj = (const float*)d_in[5];
    float* out = (float*)d_out;

    cudaFuncSetAttribute(gemm_f16<0>, cudaFuncAttributeMaxDynamicSharedMemorySize, 3 * QST);
    cudaFuncSetAttribute(gemm_f16<1>, cudaFuncAttributeMaxDynamicSharedMemorySize, 3 * QST);
    cudaFuncSetAttribute(attn_tc, cudaFuncAttributeMaxDynamicSharedMemorySize, ATT_SMEM);

    prep_all<<<(NX4 + NW1 + EMB * EMB + 255) / 256, 256>>>(x, wq, wk, wv, w_proj);

    gemm_f16<0><<<dim3(1152 / 128, BT / 128), 256, 3 * QST>>>(nullptr, nullptr);
    attn_tc<<<dim3(TT / 128, BB * HH), 256, ATT_SMEM>>>();
    gemm_f16<1><<<dim3(EMB / 128, BT / 128), 256, 3 * QST>>>(b_proj, out);
}

// round 14
// speedup vs baseline: 2.2991x; 1.0483x over previous
#include <cuda_runtime.h>
#include <cuda_bf16.h>
#include <cuda_fp16.h>
#include <cstdint>

#define BB 256
#define TT 256
#define EMB 384
#define HH 6
#define DD 64
#define BT (BB*TT)

// ---------------------------------------------------------------------------
// Scratch (__device__ globals — allocation-free rule).  Pure fp16 pipeline.
// ---------------------------------------------------------------------------
__device__ __align__(16) __half g_qhi[BB * HH * TT * DD];
__device__ __align__(16) __half g_khi[BB * HH * TT * DD];
__device__ __align__(16) __half g_vhi[BB * HH * TT * DD];
__device__ __align__(16) __half g_xhi[BT * EMB];
__device__ __align__(16) __half g_wthi[3 * HH * DD * EMB];  // [n=z*384+h*64+d][e]
__device__ __align__(16) __half g_wphi[EMB * EMB];          // [n][k]
__device__ __align__(16) __half g_atthi[BT * EMB];

// ---------------------------------------------------------------------------
// mma.sync / ldmatrix / cp.async helpers
// ---------------------------------------------------------------------------
__device__ __forceinline__ uint32_t smem_u32(const void* p) {
    uint32_t a;
    asm("{ .reg .u64 t; cvta.to.shared.u64 t, %1; cvt.u32.u64 %0, t; }"
        : "=r"(a) : "l"(p));
    return a;
}
__device__ __forceinline__ void ldm4(uint32_t* r, uint32_t addr) {
    asm volatile("ldmatrix.sync.aligned.m8n8.x4.shared.b16 {%0,%1,%2,%3}, [%4];"
        : "=r"(r[0]), "=r"(r[1]), "=r"(r[2]), "=r"(r[3]) : "r"(addr));
}
__device__ __forceinline__ void ldm4t(uint32_t* r, uint32_t addr) {
    asm volatile("ldmatrix.sync.aligned.m8n8.x4.trans.shared.b16 {%0,%1,%2,%3}, [%4];"
        : "=r"(r[0]), "=r"(r[1]), "=r"(r[2]), "=r"(r[3]) : "r"(addr));
}
__device__ __forceinline__ void mma_f16(float* c, const uint32_t* a, const uint32_t* b) {
    asm volatile(
        "mma.sync.aligned.m16n8k16.row.col.f32.f16.f16.f32 "
        "{%0,%1,%2,%3}, {%4,%5,%6,%7}, {%8,%9}, {%0,%1,%2,%3};"
        : "+f"(c[0]), "+f"(c[1]), "+f"(c[2]), "+f"(c[3])
        : "r"(a[0]), "r"(a[1]), "r"(a[2]), "r"(a[3]), "r"(b[0]), "r"(b[1]));
}
__device__ __forceinline__ void cp16(uint32_t dst, const void* src) {
    asm volatile("cp.async.cg.shared.global [%0], [%1], 16;" :: "r"(dst), "l"(src));
}
#define CP_COMMIT() asm volatile("cp.async.commit_group;" ::: "memory")
#define CP_WAIT_1() asm volatile("cp.async.wait_group 1;" ::: "memory")
#define CP_WAIT_ALL() asm volatile("cp.async.wait_group 0;" ::: "memory")

__device__ __forceinline__ uint32_t pack_h2(float lo, float hi) {
    __half2 h = __floats2half2_rn(lo, hi);
    return *(uint32_t*)&h;
}

// 64B-row tile swizzle (4 units of 16B): u ^ ((r>>1)&3)
__device__ __forceinline__ uint32_t swz(uint32_t r, uint32_t u) {
    return (r << 6) + ((u ^ ((r >> 1) & 3u)) << 4);
}
// 128B-row tile swizzle (8 units of 16B): u ^ (r&7)
__device__ __forceinline__ uint32_t swz8(uint32_t r, uint32_t u) {
    return (r << 7) + ((u ^ (r & 7u)) << 4);
}

// ---------------------------------------------------------------------------
// Prep: x -> fp16 (vectorized); weights transposed -> fp16
// ---------------------------------------------------------------------------
#define NX   (BT * EMB)
#define NX4  (NX / 4)
#define NW1  (3 * HH * DD * EMB)
__global__ void prep_all(const float* __restrict__ x,
                         const float* __restrict__ wq, const float* __restrict__ wk,
                         const float* __restrict__ wv, const float* __restrict__ wp)
{
    int i = blockIdx.x * 256 + threadIdx.x;
    if (i < NX4) {
        float4 f = *(const float4*)(x + (size_t)i * 4);
        uint32_t p0 = pack_h2(f.x, f.y);
        uint32_t p1 = pack_h2(f.z, f.w);
        *(uint2*)(g_xhi + (size_t)i * 4) = make_uint2(p0, p1);
    } else if (i < NX4 + NW1) {
        int j = i - NX4;
        int e = j % EMB;
        int d = (j / EMB) % DD;
        int h = (j / (EMB * DD)) % HH;
        int z = j / (EMB * DD * HH);
        const float* w = (z == 0) ? wq : (z == 1) ? wk : wv;
        g_wthi[j] = __float2half(w[(h * EMB + e) * DD + d]);
    } else if (i < NX4 + NW1 + EMB * EMB) {
        int j = i - NX4 - NW1;
        int k = j % EMB;
        int n = j / EMB;
        g_wphi[j] = __float2half(wp[k * EMB + n]);
    }
}

// ---------------------------------------------------------------------------
// Unified 1-term fp16 GEMM, 3-stage cp.async pipeline (R13-proven).
// MODE 0: qkv (N=1152; writes q/k/v fp16, q pre-scaled 1/8)
// MODE 1: proj (N=384; adds bias, writes fp32 out)
// ---------------------------------------------------------------------------
#define QST 16384
#define QOFF_AH 0
#define QOFF_BH 8192

template<int MODE>
__global__ __launch_bounds__(256, 2) void gemm_f16(const float* __restrict__ bias,
                                                   float* __restrict__ outp)
{
    extern __shared__ char sm[];
    const uint32_t sb = smem_u32(sm);

    const char* AhiB = (const char*)(MODE == 0 ? g_xhi : g_atthi);
    const char* BhiB = (const char*)(MODE == 0 ? g_wthi : g_wphi);

    const int tid  = threadIdx.x;
    const int wid  = tid >> 5;
    const int lane = tid & 31;
    const int m0   = blockIdx.y * 128;
    const int n0   = blockIdx.x * 128;

    const int lr = tid >> 2;
    const int lu = tid & 3;

    const int wm   = (wid >> 1) * 32;
    const int wn   = (wid & 1) * 64;
    const int a_r  = wm + (lane & 15);
    const int a_u0 = (lane >> 4);
    const int b_r  = wn + ((lane >> 4) & 1) * 8 + (lane & 7);
    const int b_u0 = (lane >> 3) & 1;

    auto issue = [&](int kc) {
        const uint32_t s0 = sb + (kc % 3) * QST;
        const int ko = kc * 64;
        #pragma unroll
        for (int j = 0; j < 2; j++) {
            int r = lr + j * 64;
            cp16(s0 + QOFF_AH + swz(r, lu), AhiB + (size_t)(m0 + r) * 768 + ko + lu * 16);
            cp16(s0 + QOFF_BH + swz(r, lu), BhiB + (size_t)(n0 + r) * 768 + ko + lu * 16);
        }
        CP_COMMIT();
    };

    issue(0);
    issue(1);

    float c[2][8][4];
    #pragma unroll
    for (int mt = 0; mt < 2; mt++)
        #pragma unroll
        for (int nt = 0; nt < 8; nt++)
            #pragma unroll
            for (int q = 0; q < 4; q++) c[mt][nt][q] = 0.0f;

    for (int kc = 0; kc < 12; kc++) {
        CP_WAIT_1();
        __syncthreads();
        if (kc + 2 < 12) issue(kc + 2);

        const uint32_t base = sb + (kc % 3) * QST;
        #pragma unroll
        for (int ks = 0; ks < 2; ks++) {
            uint32_t ahi[2][4], bhi[8][2];
            #pragma unroll
            for (int mt = 0; mt < 2; mt++) {
                uint32_t r = a_r + mt * 16;
                uint32_t u = ks * 2 + a_u0;
                ldm4(ahi[mt], base + QOFF_AH + swz(r, u));
            }
            #pragma unroll
            for (int p = 0; p < 4; p++) {
                uint32_t r = b_r + p * 16;
                uint32_t u = ks * 2 + b_u0;
                uint32_t t4[4];
                ldm4(t4, base + QOFF_BH + swz(r, u));
                bhi[2 * p][0] = t4[0]; bhi[2 * p][1] = t4[1];
                bhi[2 * p + 1][0] = t4[2]; bhi[2 * p + 1][1] = t4[3];
            }
            #pragma unroll
            for (int mt = 0; mt < 2; mt++)
                #pragma unroll
                for (int nt = 0; nt < 8; nt++)
                    mma_f16(c[mt][nt], ahi[mt], bhi[nt]);
        }
    }

    const int row0 = lane >> 2;
    const int col0 = (lane & 3) * 2;

    if (MODE == 0) {
        const int z = n0 / 384;
        const int nloc = n0 % 384;
        const float scl = (z == 0) ? 0.125f : 1.0f;
        __half* dhi = (z == 0) ? g_qhi : (z == 1) ? g_khi : g_vhi;
        #pragma unroll
        for (int mt = 0; mt < 2; mt++)
            #pragma unroll
            for (int half = 0; half < 2; half++) {
                int m = m0 + wm + mt * 16 + row0 + half * 8;
                int b = m >> 8, t = m & 255;
                #pragma unroll
                for (int nt = 0; nt < 8; nt++) {
                    int n = nloc + wn + nt * 8 + col0;
                    int h = n >> 6, d = n & 63;
                    size_t idx = (((size_t)b * HH + h) * TT + t) * DD + d;
                    *(uint32_t*)(dhi + idx) =
                        pack_h2(c[mt][nt][half * 2] * scl, c[mt][nt][half * 2 + 1] * scl);
                }
            }
    } else {
        #pragma unroll
        for (int mt = 0; mt < 2; mt++)
            #pragma unroll
            for (int half = 0; half < 2; half++) {
                int m = m0 + wm + mt * 16 + row0 + half * 8;
                #pragma unroll
                for (int nt = 0; nt < 8; nt++) {
                    int n = n0 + wn + nt * 8 + col0;
                    float2 val = make_float2(c[mt][nt][half * 2] + bias[n],
                                             c[mt][nt][half * 2 + 1] + bias[n + 1]);
                    *(float2*)(outp + (size_t)m * EMB + n) = val;
                }
            }
    }
}

// ---------------------------------------------------------------------------
// fp16 flash attention: S 1-term, PV 1-term — R13 math, now 2 CTAs/SM.
// smem: Q 16KB + 2 stages x (K 16KB + V 16KB) = 80KB (2x80 = 160 <= 227KB).
// ---------------------------------------------------------------------------
#define AQHI 0
#define AKV0 16384
#define ATT_SMEM 81920

__global__ __launch_bounds__(256, 2) void attn_tc()
{
    extern __shared__ char sm[];
    const uint32_t sb = smem_u32(sm);
    const int qt  = blockIdx.x;
    const int bh  = blockIdx.y;
    const int tid = threadIdx.x;
    const int wid = tid >> 5;
    const int lane = tid & 31;

    const __half* qhi = g_qhi + ((size_t)bh * TT + qt * 128) * DD;
    const __half* khi = g_khi + (size_t)bh * TT * DD;
    const __half* vhi = g_vhi + (size_t)bh * TT * DD;

    #pragma unroll
    for (int j = 0; j < 4; j++) {
        int idx = tid + 256 * j;
        int r = idx >> 3;
        int u = idx & 7;
        cp16(sb + AQHI + swz8(r, u), qhi + (size_t)r * DD + u * 8);
    }
    #pragma unroll
    for (int j = 0; j < 8; j++) {
        int idx = tid + 256 * j;
        int arr = idx >> 10;
        int r = (idx >> 3) & 127;
        int u = idx & 7;
        const __half* src = arr ? vhi : khi;
        cp16(sb + AKV0 + arr * 16384 + swz8(r, u), src + (size_t)r * DD + u * 8);
    }
    CP_COMMIT();
    CP_WAIT_ALL();
    __syncthreads();

    uint32_t qfh[4][4];
    {
        int ar = wid * 16 + (lane & 15);
        #pragma unroll
        for (int kc = 0; kc < 4; kc++) {
            int u = kc * 2 + (lane >> 4);
            ldm4(qfh[kc], sb + AQHI + swz8(ar, u));
        }
    }

    float o[8][4];
    #pragma unroll
    for (int nt = 0; nt < 8; nt++)
        #pragma unroll
        for (int q = 0; q < 4; q++) o[nt][q] = 0.0f;
    float mx[2] = {-1e30f, -1e30f};
    float lsum[2] = {0.0f, 0.0f};

    for (int kt = 0; kt <= qt; kt++) {
        const uint32_t kvb = sb + AKV0 + (kt & 1) * 32768;

        if (kt < qt) {
            #pragma unroll
            for (int j = 0; j < 8; j++) {
                int idx = tid + 256 * j;
                int arr = idx >> 10;
                int r = (idx >> 3) & 127;
                int u = idx & 7;
                const __half* src = arr ? vhi : khi;
                cp16(sb + AKV0 + ((kt + 1) & 1) * 32768 + arr * 16384 + swz8(r, u),
                     src + ((size_t)(kt + 1) * 128 + r) * DD + u * 8);
            }
            CP_COMMIT();
        }

        float s[16][4];
        #pragma unroll
        for (int nt = 0; nt < 16; nt++)
            #pragma unroll
            for (int q = 0; q < 4; q++) s[nt][q] = 0.0f;

        #pragma unroll
        for (int np = 0; np < 8; np++) {
            int br = np * 16 + ((lane >> 4) & 1) * 8 + (lane & 7);
            #pragma unroll
            for (int kc = 0; kc < 4; kc++) {
                int u = kc * 2 + ((lane >> 3) & 1);
                uint32_t th[4];
                ldm4(th, kvb + swz8(br, u));
                uint32_t b0h[2] = {th[0], th[1]}, b1h[2] = {th[2], th[3]};
                mma_f16(s[2 * np], qfh[kc], b0h);
                mma_f16(s[2 * np + 1], qfh[kc], b1h);
            }
        }

        if (kt == qt) {
            #pragma unroll
            for (int nt = 0; nt < 16; nt++)
                #pragma unroll
                for (int q = 0; q < 4; q++) {
                    int col = nt * 8 + (lane & 3) * 2 + (q & 1);
                    int row = wid * 16 + (lane >> 2) + (q >> 1) * 8;
                    if (col > row) s[nt][q] = -1e30f;
                }
        }

        float al[2];
        #pragma unroll
        for (int hf = 0; hf < 2; hf++) {
            float rm = -1e30f;
            #pragma unroll
            for (int nt = 0; nt < 16; nt++)
                rm = fmaxf(rm, fmaxf(s[nt][hf * 2], s[nt][hf * 2 + 1]));
            rm = fmaxf(rm, __shfl_xor_sync(0xffffffffu, rm, 1));
            rm = fmaxf(rm, __shfl_xor_sync(0xffffffffu, rm, 2));
            float mn = fmaxf(mx[hf], rm);
            al[hf] = __expf(mx[hf] - mn);
            mx[hf] = mn;
            float ps = 0.0f;
            #pragma unroll
            for (int nt = 0; nt < 16; nt++) {
                s[nt][hf * 2]     = __expf(s[nt][hf * 2] - mn);
                s[nt][hf * 2 + 1] = __expf(s[nt][hf * 2 + 1] - mn);
                ps += s[nt][hf * 2] + s[nt][hf * 2 + 1];
            }
            ps += __shfl_xor_sync(0xffffffffu, ps, 1);
            ps += __shfl_xor_sync(0xffffffffu, ps, 2);
            lsum[hf] = lsum[hf] * al[hf] + ps;
        }
        #pragma unroll
        for (int nt = 0; nt < 8; nt++) {
            o[nt][0] *= al[0]; o[nt][1] *= al[0];
            o[nt][2] *= al[1]; o[nt][3] *= al[1];
        }

        #pragma unroll
        for (int kc = 0; kc < 8; kc++) {
            uint32_t ah[4];
            ah[0] = pack_h2(s[2 * kc][0], s[2 * kc][1]);
            ah[1] = pack_h2(s[2 * kc][2], s[2 * kc][3]);
            ah[2] = pack_h2(s[2 * kc + 1][0], s[2 * kc + 1][1]);
            ah[3] = pack_h2(s[2 * kc + 1][2], s[2 * kc + 1][3]);

            int vr = kc * 16 + ((lane >> 3) & 1) * 8 + (lane & 7);
            #pragma unroll
            for (int ntp = 0; ntp < 4; ntp++) {
                int u = ntp * 2 + (lane >> 4);
                uint32_t th[4];
                ldm4t(th, kvb + 16384 + swz8(vr, u));
                uint32_t b0h[2] = {th[0], th[1]}, b1h[2] = {th[2], th[3]};
                mma_f16(o[2 * ntp], ah, b0h);
                mma_f16(o[2 * ntp + 1], ah, b1h);
            }
        }

        if (kt < qt) {
            CP_WAIT_ALL();
            __syncthreads();
        }
    }

    const int b = bh / HH, h = bh % HH;
    #pragma unroll
    for (int hf = 0; hf < 2; hf++) {
        float inv = 1.0f / lsum[hf];
        int t = qt * 128 + wid * 16 + (lane >> 2) + hf * 8;
        size_t rowb = ((size_t)b * TT + t) * EMB + h * 64 + (lane & 3) * 2;
        #pragma unroll
        for (int nt = 0; nt < 8; nt++)
            *(uint32_t*)(g_atthi + rowb + nt * 8) =
                pack_h2(o[nt][hf * 2] * inv, o[nt][hf * 2 + 1] * inv);
    }
}

// ---------------------------------------------------------------------------
extern "C" void kernel_launch(void* const* d_in, const int* in_sizes, int n_in,
                              void* d_out, int out_size)
{
    const float* x      = (const float*)d_in[0];
    const float* wq     = (const float*)d_in[1];
    const float* wk     = (const float*)d_in[2];
    const float* wv     = (const float*)d_in[3];
    const float* w_proj = (const float*)d_in[4];
    const float* b_proj = (const float*)d_in[5];
    float* out = (float*)d_out;

    cudaFuncSetAttribute(gemm_f16<0>, cudaFuncAttributeMaxDynamicSharedMemorySize, 3 * QST);
    cudaFuncSetAttribute(gemm_f16<1>, cudaFuncAttributeMaxDynamicSharedMemorySize, 3 * QST);
    cudaFuncSetAttribute(attn_tc, cudaFuncAttributeMaxDynamicSharedMemorySize, ATT_SMEM);

    prep_all<<<(NX4 + NW1 + EMB * EMB + 255) / 256, 256>>>(x, wq, wk, wv, w_proj);

    gemm_f16<0><<<dim3(1152 / 128, BT / 128), 256, 3 * QST>>>(nullptr, nullptr);
    attn_tc<<<dim3(TT / 128, BB * HH), 256, ATT_SMEM>>>();
    gemm_f16<1><<<dim3(EMB / 128, BT / 128), 256, 3 * QST>>>(b_proj, out);
}

// round 15
// speedup vs baseline: 2.3517x; 1.0229x over previous
#include <cuda_runtime.h>
#include <cuda_bf16.h>
#include <cuda_fp16.h>
#include <cstdint>

#define BB 256
#define TT 256
#define EMB 384
#define HH 6
#define DD 64
#define BT (BB*TT)

// ---------------------------------------------------------------------------
// Scratch (__device__ globals — allocation-free rule).  Pure fp16 pipeline.
// ---------------------------------------------------------------------------
__device__ __align__(16) __half g_qhi[BB * HH * TT * DD];
__device__ __align__(16) __half g_khi[BB * HH * TT * DD];
__device__ __align__(16) __half g_vhi[BB * HH * TT * DD];
__device__ __align__(16) __half g_xhi[BT * EMB];
__device__ __align__(16) __half g_wthi[3 * HH * DD * EMB];  // [n=z*384+h*64+d][e]
__device__ __align__(16) __half g_wphi[EMB * EMB];          // [n][k]
__device__ __align__(16) __half g_atthi[BT * EMB];

// ---------------------------------------------------------------------------
// mma.sync / ldmatrix / cp.async helpers
// ---------------------------------------------------------------------------
__device__ __forceinline__ uint32_t smem_u32(const void* p) {
    uint32_t a;
    asm("{ .reg .u64 t; cvta.to.shared.u64 t, %1; cvt.u32.u64 %0, t; }"
        : "=r"(a) : "l"(p));
    return a;
}
__device__ __forceinline__ void ldm4(uint32_t* r, uint32_t addr) {
    asm volatile("ldmatrix.sync.aligned.m8n8.x4.shared.b16 {%0,%1,%2,%3}, [%4];"
        : "=r"(r[0]), "=r"(r[1]), "=r"(r[2]), "=r"(r[3]) : "r"(addr));
}
__device__ __forceinline__ void ldm4t(uint32_t* r, uint32_t addr) {
    asm volatile("ldmatrix.sync.aligned.m8n8.x4.trans.shared.b16 {%0,%1,%2,%3}, [%4];"
        : "=r"(r[0]), "=r"(r[1]), "=r"(r[2]), "=r"(r[3]) : "r"(addr));
}
__device__ __forceinline__ void mma_f16(float* c, const uint32_t* a, const uint32_t* b) {
    asm volatile(
        "mma.sync.aligned.m16n8k16.row.col.f32.f16.f16.f32 "
        "{%0,%1,%2,%3}, {%4,%5,%6,%7}, {%8,%9}, {%0,%1,%2,%3};"
        : "+f"(c[0]), "+f"(c[1]), "+f"(c[2]), "+f"(c[3])
        : "r"(a[0]), "r"(a[1]), "r"(a[2]), "r"(a[3]), "r"(b[0]), "r"(b[1]));
}
__device__ __forceinline__ void cp16(uint32_t dst, const void* src) {
    asm volatile("cp.async.cg.shared.global [%0], [%1], 16;" :: "r"(dst), "l"(src));
}
#define CP_COMMIT() asm volatile("cp.async.commit_group;" ::: "memory")
#define CP_WAIT_1() asm volatile("cp.async.wait_group 1;" ::: "memory")
#define CP_WAIT_ALL() asm volatile("cp.async.wait_group 0;" ::: "memory")

__device__ __forceinline__ uint32_t pack_h2(float lo, float hi) {
    __half2 h = __floats2half2_rn(lo, hi);
    return *(uint32_t*)&h;
}

// 128B-row tile swizzle (8 units of 16B): u ^ (r&7)
__device__ __forceinline__ uint32_t swz8(uint32_t r, uint32_t u) {
    return (r << 7) + ((u ^ (r & 7u)) << 4);
}

// ---------------------------------------------------------------------------
// Prep: x -> fp16 (vectorized); weights transposed -> fp16
// ---------------------------------------------------------------------------
#define NX   (BT * EMB)
#define NX4  (NX / 4)
#define NW1  (3 * HH * DD * EMB)
__global__ void prep_all(const float* __restrict__ x,
                         const float* __restrict__ wq, const float* __restrict__ wk,
                         const float* __restrict__ wv, const float* __restrict__ wp)
{
    int i = blockIdx.x * 256 + threadIdx.x;
    if (i < NX4) {
        float4 f = *(const float4*)(x + (size_t)i * 4);
        uint32_t p0 = pack_h2(f.x, f.y);
        uint32_t p1 = pack_h2(f.z, f.w);
        *(uint2*)(g_xhi + (size_t)i * 4) = make_uint2(p0, p1);
    } else if (i < NX4 + NW1) {
        int j = i - NX4;
        int e = j % EMB;
        int d = (j / EMB) % DD;
        int h = (j / (EMB * DD)) % HH;
        int z = j / (EMB * DD * HH);
        const float* w = (z == 0) ? wq : (z == 1) ? wk : wv;
        g_wthi[j] = __float2half(w[(h * EMB + e) * DD + d]);
    } else if (i < NX4 + NW1 + EMB * EMB) {
        int j = i - NX4 - NW1;
        int k = j % EMB;
        int n = j / EMB;
        g_wphi[j] = __float2half(wp[k * EMB + n]);
    }
}

// ---------------------------------------------------------------------------
// Unified 1-term fp16 GEMM, 3-stage cp.async pipeline, K-chunk 64.
// C[M,N] = A[M,384] x B[384,N].  6 chunks of 64 over K=384.
// Stage = Ahi(16KB)+Bhi(16KB) = 32KB (swz8 layout); 3 stages = 96KB; 2 CTAs/SM.
// MODE 0: qkv (N=1152; writes q/k/v fp16, q pre-scaled 1/8)
// MODE 1: proj (N=384; adds bias, writes fp32 out)
// ---------------------------------------------------------------------------
#define QST 32768
#define QOFF_AH 0
#define QOFF_BH 16384

template<int MODE>
__global__ __launch_bounds__(256, 2) void gemm_f16(const float* __restrict__ bias,
                                                   float* __restrict__ outp)
{
    extern __shared__ char sm[];
    const uint32_t sb = smem_u32(sm);

    const char* AhiB = (const char*)(MODE == 0 ? g_xhi : g_atthi);
    const char* BhiB = (const char*)(MODE == 0 ? g_wthi : g_wphi);

    const int tid  = threadIdx.x;
    const int wid  = tid >> 5;
    const int lane = tid & 31;
    const int m0   = blockIdx.y * 128;
    const int n0   = blockIdx.x * 128;

    const int wm   = (wid >> 1) * 32;
    const int wn   = (wid & 1) * 64;
    const int a_r  = wm + (lane & 15);
    const int a_u0 = (lane >> 4);
    const int b_r  = wn + ((lane >> 4) & 1) * 8 + (lane & 7);
    const int b_u0 = (lane >> 3) & 1;

    // issue chunk kc (K elems kc*64 .. kc*64+63) into stage kc%3.
    // Per array: 128 rows x 8 units of 16B = 1024 units; 4 per thread.
    auto issue = [&](int kc) {
        const uint32_t s0 = sb + (kc % 3) * QST;
        const int ko = kc * 128;   // byte offset within row (64 fp16)
        #pragma unroll
        for (int j = 0; j < 4; j++) {
            int idx = tid + 256 * j;
            int r = idx >> 3;
            int u = idx & 7;
            cp16(s0 + QOFF_AH + swz8(r, u), AhiB + (size_t)(m0 + r) * 768 + ko + u * 16);
            cp16(s0 + QOFF_BH + swz8(r, u), BhiB + (size_t)(n0 + r) * 768 + ko + u * 16);
        }
        CP_COMMIT();
    };

    issue(0);
    issue(1);

    float c[2][8][4];
    #pragma unroll
    for (int mt = 0; mt < 2; mt++)
        #pragma unroll
        for (int nt = 0; nt < 8; nt++)
            #pragma unroll
            for (int q = 0; q < 4; q++) c[mt][nt][q] = 0.0f;

    for (int kc = 0; kc < 6; kc++) {
        CP_WAIT_1();
        __syncthreads();
        if (kc + 2 < 6) issue(kc + 2);

        const uint32_t base = sb + (kc % 3) * QST;
        #pragma unroll
        for (int ks = 0; ks < 4; ks++) {
            uint32_t ahi[2][4], bhi[8][2];
            #pragma unroll
            for (int mt = 0; mt < 2; mt++) {
                uint32_t r = a_r + mt * 16;
                uint32_t u = ks * 2 + a_u0;
                ldm4(ahi[mt], base + QOFF_AH + swz8(r, u));
            }
            #pragma unroll
            for (int p = 0; p < 4; p++) {
                uint32_t r = b_r + p * 16;
                uint32_t u = ks * 2 + b_u0;
                uint32_t t4[4];
                ldm4(t4, base + QOFF_BH + swz8(r, u));
                bhi[2 * p][0] = t4[0]; bhi[2 * p][1] = t4[1];
                bhi[2 * p + 1][0] = t4[2]; bhi[2 * p + 1][1] = t4[3];
            }
            #pragma unroll
            for (int mt = 0; mt < 2; mt++)
                #pragma unroll
                for (int nt = 0; nt < 8; nt++)
                    mma_f16(c[mt][nt], ahi[mt], bhi[nt]);
        }
    }

    const int row0 = lane >> 2;
    const int col0 = (lane & 3) * 2;

    if (MODE == 0) {
        const int z = n0 / 384;
        const int nloc = n0 % 384;
        const float scl = (z == 0) ? 0.125f : 1.0f;
        __half* dhi = (z == 0) ? g_qhi : (z == 1) ? g_khi : g_vhi;
        #pragma unroll
        for (int mt = 0; mt < 2; mt++)
            #pragma unroll
            for (int half = 0; half < 2; half++) {
                int m = m0 + wm + mt * 16 + row0 + half * 8;
                int b = m >> 8, t = m & 255;
                #pragma unroll
                for (int nt = 0; nt < 8; nt++) {
                    int n = nloc + wn + nt * 8 + col0;
                    int h = n >> 6, d = n & 63;
                    size_t idx = (((size_t)b * HH + h) * TT + t) * DD + d;
                    *(uint32_t*)(dhi + idx) =
                        pack_h2(c[mt][nt][half * 2] * scl, c[mt][nt][half * 2 + 1] * scl);
                }
            }
    } else {
        #pragma unroll
        for (int mt = 0; mt < 2; mt++)
            #pragma unroll
            for (int half = 0; half < 2; half++) {
                int m = m0 + wm + mt * 16 + row0 + half * 8;
                #pragma unroll
                for (int nt = 0; nt < 8; nt++) {
                    int n = n0 + wn + nt * 8 + col0;
                    float2 val = make_float2(c[mt][nt][half * 2] + bias[n],
                                             c[mt][nt][half * 2 + 1] + bias[n + 1]);
                    *(float2*)(outp + (size_t)m * EMB + n) = val;
                }
            }
    }
}

// ---------------------------------------------------------------------------
// fp16 flash attention: S 1-term, PV 1-term — exact R14-proven version.
// smem: Q 16KB + 2 stages x (K 16KB + V 16KB) = 80KB; 2 CTAs/SM.
// ---------------------------------------------------------------------------
#define AQHI 0
#define AKV0 16384
#define ATT_SMEM 81920

__global__ __launch_bounds__(256, 2) void attn_tc()
{
    extern __shared__ char sm[];
    const uint32_t sb = smem_u32(sm);
    const int qt  = blockIdx.x;
    const int bh  = blockIdx.y;
    const int tid = threadIdx.x;
    const int wid = tid >> 5;
    const int lane = tid & 31;

    const __half* qhi = g_qhi + ((size_t)bh * TT + qt * 128) * DD;
    const __half* khi = g_khi + (size_t)bh * TT * DD;
    const __half* vhi = g_vhi + (size_t)bh * TT * DD;

    #pragma unroll
    for (int j = 0; j < 4; j++) {
        int idx = tid + 256 * j;
        int r = idx >> 3;
        int u = idx & 7;
        cp16(sb + AQHI + swz8(r, u), qhi + (size_t)r * DD + u * 8);
    }
    #pragma unroll
    for (int j = 0; j < 8; j++) {
        int idx = tid + 256 * j;
        int arr = idx >> 10;
        int r = (idx >> 3) & 127;
        int u = idx & 7;
        const __half* src = arr ? vhi : khi;
        cp16(sb + AKV0 + arr * 16384 + swz8(r, u), src + (size_t)r * DD + u * 8);
    }
    CP_COMMIT();
    CP_WAIT_ALL();
    __syncthreads();

    uint32_t qfh[4][4];
    {
        int ar = wid * 16 + (lane & 15);
        #pragma unroll
        for (int kc = 0; kc < 4; kc++) {
            int u = kc * 2 + (lane >> 4);
            ldm4(qfh[kc], sb + AQHI + swz8(ar, u));
        }
    }

    float o[8][4];
    #pragma unroll
    for (int nt = 0; nt < 8; nt++)
        #pragma unroll
        for (int q = 0; q < 4; q++) o[nt][q] = 0.0f;
    float mx[2] = {-1e30f, -1e30f};
    float lsum[2] = {0.0f, 0.0f};

    for (int kt = 0; kt <= qt; kt++) {
        const uint32_t kvb = sb + AKV0 + (kt & 1) * 32768;

        if (kt < qt) {
            #pragma unroll
            for (int j = 0; j < 8; j++) {
                int idx = tid + 256 * j;
                int arr = idx >> 10;
                int r = (idx >> 3) & 127;
                int u = idx & 7;
                const __half* src = arr ? vhi : khi;
                cp16(sb + AKV0 + ((kt + 1) & 1) * 32768 + arr * 16384 + swz8(r, u),
                     src + ((size_t)(kt + 1) * 128 + r) * DD + u * 8);
            }
            CP_COMMIT();
        }

        float s[16][4];
        #pragma unroll
        for (int nt = 0; nt < 16; nt++)
            #pragma unroll
            for (int q = 0; q < 4; q++) s[nt][q] = 0.0f;

        #pragma unroll
        for (int np = 0; np < 8; np++) {
            int br = np * 16 + ((lane >> 4) & 1) * 8 + (lane & 7);
            #pragma unroll
            for (int kc = 0; kc < 4; kc++) {
                int u = kc * 2 + ((lane >> 3) & 1);
                uint32_t th[4];
                ldm4(th, kvb + swz8(br, u));
                uint32_t b0h[2] = {th[0], th[1]}, b1h[2] = {th[2], th[3]};
                mma_f16(s[2 * np], qfh[kc], b0h);
                mma_f16(s[2 * np + 1], qfh[kc], b1h);
            }
        }

        if (kt == qt) {
            #pragma unroll
            for (int nt = 0; nt < 16; nt++)
                #pragma unroll
                for (int q = 0; q < 4; q++) {
                    int col = nt * 8 + (lane & 3) * 2 + (q & 1);
                    int row = wid * 16 + (lane >> 2) + (q >> 1) * 8;
                    if (col > row) s[nt][q] = -1e30f;
                }
        }

        float al[2];
        #pragma unroll
        for (int hf = 0; hf < 2; hf++) {
            float rm = -1e30f;
            #pragma unroll
            for (int nt = 0; nt < 16; nt++)
                rm = fmaxf(rm, fmaxf(s[nt][hf * 2], s[nt][hf * 2 + 1]));
            rm = fmaxf(rm, __shfl_xor_sync(0xffffffffu, rm, 1));
            rm = fmaxf(rm, __shfl_xor_sync(0xffffffffu, rm, 2));
            float mn = fmaxf(mx[hf], rm);
            al[hf] = __expf(mx[hf] - mn);
            mx[hf] = mn;
            float ps = 0.0f;
            #pragma unroll
            for (int nt = 0; nt < 16; nt++) {
                s[nt][hf * 2]     = __expf(s[nt][hf * 2] - mn);
                s[nt][hf * 2 + 1] = __expf(s[nt][hf * 2 + 1] - mn);
                ps += s[nt][hf * 2] + s[nt][hf * 2 + 1];
            }
            ps += __shfl_xor_sync(0xffffffffu, ps, 1);
            ps += __shfl_xor_sync(0xffffffffu, ps, 2);
            lsum[hf] = lsum[hf] * al[hf] + ps;
        }
        #pragma unroll
        for (int nt = 0; nt < 8; nt++) {
            o[nt][0] *= al[0]; o[nt][1] *= al[0];
            o[nt][2] *= al[1]; o[nt][3] *= al[1];
        }

        #pragma unroll
        for (int kc = 0; kc < 8; kc++) {
            uint32_t ah[4];
            ah[0] = pack_h2(s[2 * kc][0], s[2 * kc][1]);
            ah[1] = pack_h2(s[2 * kc][2], s[2 * kc][3]);
            ah[2] = pack_h2(s[2 * kc + 1][0], s[2 * kc + 1][1]);
            ah[3] = pack_h2(s[2 * kc + 1][2], s[2 * kc + 1][3]);

            int vr = kc * 16 + ((lane >> 3) & 1) * 8 + (lane & 7);
            #pragma unroll
            for (int ntp = 0; ntp < 4; ntp++) {
                int u = ntp * 2 + (lane >> 4);
                uint32_t th[4];
                ldm4t(th, kvb + 16384 + swz8(vr, u));
                uint32_t b0h[2] = {th[0], th[1]}, b1h[2] = {th[2], th[3]};
                mma_f16(o[2 * ntp], ah, b0h);
                mma_f16(o[2 * ntp + 1], ah, b1h);
            }
        }

        if (kt < qt) {
            CP_WAIT_ALL();
            __syncthreads();
        }
    }

    const int b = bh / HH, h = bh % HH;
    #pragma unroll
    for (int hf = 0; hf < 2; hf++) {
        float inv = 1.0f / lsum[hf];
        int t = qt * 128 + wid * 16 + (lane >> 2) + hf * 8;
        size_t rowb = ((size_t)b * TT + t) * EMB + h * 64 + (lane & 3) * 2;
        #pragma unroll
        for (int nt = 0; nt < 8; nt++)
            *(uint32_t*)(g_atthi + rowb + nt * 8) =
                pack_h2(o[nt][hf * 2] * inv, o[nt][hf * 2 + 1] * inv);
    }
}

// ---------------------------------------------------------------------------
extern "C" void kernel_launch(void* const* d_in, const int* in_sizes, int n_in,
                              void* d_out, int out_size)
{
    const float* x      = (const float*)d_in[0];
    const float* wq     = (const float*)d_in[1];
    const float* wk     = (const float*)d_in[2];
    const float* wv     = (const float*)d_in[3];
    const float* w_proj = (const float*)d_in[4];
    const float* b_proj = (const float*)d_in[5];
    float* out = (float*)d_out;

    cudaFuncSetAttribute(gemm_f16<0>, cudaFuncAttributeMaxDynamicSharedMemorySize, 3 * QST);
    cudaFuncSetAttribute(gemm_f16<1>, cudaFuncAttributeMaxDynamicSharedMemorySize, 3 * QST);
    cudaFuncSetAttribute(attn_tc, cudaFuncAttributeMaxDynamicSharedMemorySize, ATT_SMEM);

    prep_all<<<(NX4 + NW1 + EMB * EMB + 255) / 256, 256>>>(x, wq, wk, wv, w_proj);

    gemm_f16<0><<<dim3(1152 / 128, BT / 128), 256, 3 * QST>>>(nullptr, nullptr);
    attn_tc<<<dim3(TT / 128, BB * HH), 256, ATT_SMEM>>>();
    gemm_f16<1><<<dim3(EMB / 128, BT / 128), 256, 3 * QST>>>(b_proj, out);
}